// round 1
// baseline (speedup 1.0000x reference)
#include <cuda_runtime.h>
#include <math.h>
#include <stdint.h>

// Problem constants
#define BATCH   2
#define SEQ     2048
#define DMODEL  1024
#define NHEADS  16
#define DK      64
#define MROWS   (BATCH * SEQ)          // 4096
#define OUT_ELEMS   ((size_t)MROWS * DMODEL)               // 4,194,304
#define ATTN_ELEMS  ((size_t)BATCH * NHEADS * SEQ * SEQ)   // 134,217,728

// Scratch (device globals -- no allocation)
__device__ static float g_q [MROWS * DMODEL];
__device__ static float g_k [MROWS * DMODEL];
__device__ static float g_v [MROWS * DMODEL];
__device__ static float g_ao[MROWS * DMODEL];

// ---------------------------------------------------------------------------
// SGEMM: C[M,N] = A[M,K] @ W[N,K]^T (+ bias[N] if given)
// BM=BN=128, BK=8, 256 threads, 8x8 microtile.
// M,N,K must be multiples of 128/128/8 (they are: 4096/1024/1024).
// ---------------------------------------------------------------------------
__global__ __launch_bounds__(256)
void sgemm_nt(const float* __restrict__ A, const float* __restrict__ W,
              float* __restrict__ C, const float* __restrict__ bias,
              int Mi, int Ni, int Ki)
{
    __shared__ float As[8][128];
    __shared__ float Bs[8][128];

    const int t  = threadIdx.x;
    const int m0 = blockIdx.y * 128;
    const int n0 = blockIdx.x * 128;

    const int lr = t >> 1;          // 0..127 : row within tile
    const int lc = (t & 1) * 4;     // 0 or 4 : k offset
    const float* aptr = A + (size_t)(m0 + lr) * Ki + lc;
    const float* bptr = W + (size_t)(n0 + lr) * Ki + lc;

    const int tx = t & 15, ty = t >> 4;
    const int mr = ty * 8, nr = tx * 8;

    float acc[8][8];
#pragma unroll
    for (int i = 0; i < 8; ++i)
#pragma unroll
        for (int j = 0; j < 8; ++j) acc[i][j] = 0.f;

    for (int k0 = 0; k0 < Ki; k0 += 8) {
        float4 av = *(const float4*)(aptr + k0);
        float4 bv = *(const float4*)(bptr + k0);
        As[lc + 0][lr] = av.x; As[lc + 1][lr] = av.y;
        As[lc + 2][lr] = av.z; As[lc + 3][lr] = av.w;
        Bs[lc + 0][lr] = bv.x; Bs[lc + 1][lr] = bv.y;
        Bs[lc + 2][lr] = bv.z; Bs[lc + 3][lr] = bv.w;
        __syncthreads();

#pragma unroll
        for (int k = 0; k < 8; ++k) {
            float4 a0 = *(const float4*)&As[k][mr];
            float4 a1 = *(const float4*)&As[k][mr + 4];
            float4 b0 = *(const float4*)&Bs[k][nr];
            float4 b1 = *(const float4*)&Bs[k][nr + 4];
            float aa[8] = {a0.x, a0.y, a0.z, a0.w, a1.x, a1.y, a1.z, a1.w};
            float bb[8] = {b0.x, b0.y, b0.z, b0.w, b1.x, b1.y, b1.z, b1.w};
#pragma unroll
            for (int i = 0; i < 8; ++i)
#pragma unroll
                for (int j = 0; j < 8; ++j)
                    acc[i][j] += aa[i] * bb[j];
        }
        __syncthreads();
    }

    float bv8[8];
#pragma unroll
    for (int j = 0; j < 8; ++j) bv8[j] = bias ? bias[n0 + nr + j] : 0.f;

#pragma unroll
    for (int i = 0; i < 8; ++i) {
        float* crow = C + (size_t)(m0 + mr + i) * Ni + n0 + nr;
        float4 c0, c1;
        c0.x = acc[i][0] + bv8[0]; c0.y = acc[i][1] + bv8[1];
        c0.z = acc[i][2] + bv8[2]; c0.w = acc[i][3] + bv8[3];
        c1.x = acc[i][4] + bv8[4]; c1.y = acc[i][5] + bv8[5];
        c1.z = acc[i][6] + bv8[6]; c1.w = acc[i][7] + bv8[7];
        *(float4*)(crow)     = c0;
        *(float4*)(crow + 4) = c1;
    }
}

// ---------------------------------------------------------------------------
// Causal attention per (b, h, q-tile of 64 rows).
// Two passes: (1) row max + sumexp over causal key tiles,
//             (2) recompute scores, write normalized attn, accumulate P@V.
// Smem (floats, stride 68 to dodge bank conflicts):
//   Qt[64][68] (Q transposed: Qt[d][i])   Kt[64][68] (K transposed: Kt[d][j])
//   Ps[64][68] (P transposed: Ps[j][i])   Vs[64][68] (V: Vs[j][d])
//   mrow[64], lrow[64]
// ---------------------------------------------------------------------------
#define TQ 64
#define TK 64
#define STRD 68
#define NEG_BIG (-1.0e30f)
#define SMEM_ATTN_FLOATS (4 * 64 * STRD + 128)
#define SMEM_ATTN_BYTES  (SMEM_ATTN_FLOATS * 4)

__global__ __launch_bounds__(256)
void attn_kernel(const float* __restrict__ q, const float* __restrict__ kmat,
                 const float* __restrict__ vmat, float* __restrict__ attn,
                 float* __restrict__ ao, int write_attn)
{
    extern __shared__ float sm[];
    float* Qt   = sm;
    float* Kt   = Qt + 64 * STRD;
    float* Ps   = Kt + 64 * STRD;
    float* Vs   = Ps + 64 * STRD;
    float* mrow = Vs + 64 * STRD;
    float* lrow = mrow + 64;

    const int qt = blockIdx.x;       // 0..31
    const int h  = blockIdx.y;       // 0..15
    const int b  = blockIdx.z;       // 0..1
    const int q0 = qt * TQ;
    const int t  = threadIdx.x;      // 256
    const int ty = t >> 4, tx = t & 15;
    const int i0 = ty * 4, j0 = tx * 4;     // 4x4 microtile
    const float scale = 0.125f;             // 1/sqrt(64)

    const int lrw = t >> 2;               // 0..63 : loader row
    const int lds = (t & 3) * 16;         // 0,16,32,48 : loader col offset

    // Load Q tile transposed: Qt[d][i]
    {
        const float* src = q + ((size_t)(b * SEQ + q0 + lrw)) * DMODEL + h * DK + lds;
#pragma unroll
        for (int u = 0; u < 16; u += 4) {
            float4 v4 = *(const float4*)(src + u);
            Qt[(lds + u + 0) * STRD + lrw] = v4.x;
            Qt[(lds + u + 1) * STRD + lrw] = v4.y;
            Qt[(lds + u + 2) * STRD + lrw] = v4.z;
            Qt[(lds + u + 3) * STRD + lrw] = v4.w;
        }
    }
    if (t < 64) { mrow[t] = NEG_BIG; lrow[t] = 0.f; }
    __syncthreads();

    // ---------------- Pass 1: row max + sumexp ----------------
    for (int kt = 0; kt <= qt; ++kt) {
        const int k0 = kt * TK;
        {
            const float* src = kmat + ((size_t)(b * SEQ + k0 + lrw)) * DMODEL + h * DK + lds;
#pragma unroll
            for (int u = 0; u < 16; u += 4) {
                float4 v4 = *(const float4*)(src + u);
                Kt[(lds + u + 0) * STRD + lrw] = v4.x;
                Kt[(lds + u + 1) * STRD + lrw] = v4.y;
                Kt[(lds + u + 2) * STRD + lrw] = v4.z;
                Kt[(lds + u + 3) * STRD + lrw] = v4.w;
            }
        }
        __syncthreads();

        float s[4][4];
#pragma unroll
        for (int i = 0; i < 4; ++i)
#pragma unroll
            for (int j = 0; j < 4; ++j) s[i][j] = 0.f;

#pragma unroll 8
        for (int d = 0; d < DK; ++d) {
            float4 aq = *(const float4*)&Qt[d * STRD + i0];
            float4 bk = *(const float4*)&Kt[d * STRD + j0];
            float aa[4] = {aq.x, aq.y, aq.z, aq.w};
            float bb[4] = {bk.x, bk.y, bk.z, bk.w};
#pragma unroll
            for (int i = 0; i < 4; ++i)
#pragma unroll
                for (int j = 0; j < 4; ++j) s[i][j] += aa[i] * bb[j];
        }

#pragma unroll
        for (int i = 0; i < 4; ++i)
#pragma unroll
            for (int j = 0; j < 4; ++j) {
                float v = s[i][j] * scale;
                if (k0 + j0 + j > q0 + i0 + i) v = NEG_BIG;
                Ps[(j0 + j) * STRD + (i0 + i)] = v;
            }
        __syncthreads();

        if (t < 64) {
            float mo = mrow[t];
            float tm = mo;
#pragma unroll 16
            for (int j = 0; j < TK; ++j) tm = fmaxf(tm, Ps[j * STRD + t]);
            float sum = 0.f;
#pragma unroll 16
            for (int j = 0; j < TK; ++j) sum += __expf(Ps[j * STRD + t] - tm);
            lrow[t] = lrow[t] * __expf(mo - tm) + sum;
            mrow[t] = tm;
        }
        __syncthreads();
    }
    if (t < 64) lrow[t] = 1.0f / lrow[t];   // now holds 1/l
    __syncthreads();

    // ---------------- Pass 2: attn write + P@V ----------------
    float o[4][4];
#pragma unroll
    for (int i = 0; i < 4; ++i)
#pragma unroll
        for (int j = 0; j < 4; ++j) o[i][j] = 0.f;

    float* attn_base = write_attn
        ? attn + ((size_t)(b * NHEADS + h) * SEQ + q0) * SEQ
        : (float*)0;

    for (int kt = 0; kt < SEQ / TK; ++kt) {
        const int k0 = kt * TK;
        if (kt > qt) {                       // fully masked tile -> zeros
            if (write_attn) {
                float4 z = make_float4(0.f, 0.f, 0.f, 0.f);
                float* dst = attn_base + (size_t)lrw * SEQ + k0 + lds;
                *(float4*)(dst + 0)  = z;
                *(float4*)(dst + 4)  = z;
                *(float4*)(dst + 8)  = z;
                *(float4*)(dst + 12) = z;
            }
            continue;
        }
        // load K (transposed) and V tiles
        {
            const float* ksrc = kmat + ((size_t)(b * SEQ + k0 + lrw)) * DMODEL + h * DK + lds;
            const float* vsrc = vmat + ((size_t)(b * SEQ + k0 + lrw)) * DMODEL + h * DK + lds;
#pragma unroll
            for (int u = 0; u < 16; u += 4) {
                float4 v4 = *(const float4*)(ksrc + u);
                Kt[(lds + u + 0) * STRD + lrw] = v4.x;
                Kt[(lds + u + 1) * STRD + lrw] = v4.y;
                Kt[(lds + u + 2) * STRD + lrw] = v4.z;
                Kt[(lds + u + 3) * STRD + lrw] = v4.w;
                *(float4*)&Vs[lrw * STRD + lds + u] = *(const float4*)(vsrc + u);
            }
        }
        __syncthreads();

        float s[4][4];
#pragma unroll
        for (int i = 0; i < 4; ++i)
#pragma unroll
            for (int j = 0; j < 4; ++j) s[i][j] = 0.f;

#pragma unroll 8
        for (int d = 0; d < DK; ++d) {
            float4 aq = *(const float4*)&Qt[d * STRD + i0];
            float4 bk = *(const float4*)&Kt[d * STRD + j0];
            float aa[4] = {aq.x, aq.y, aq.z, aq.w};
            float bb[4] = {bk.x, bk.y, bk.z, bk.w};
#pragma unroll
            for (int i = 0; i < 4; ++i)
#pragma unroll
                for (int j = 0; j < 4; ++j) s[i][j] += aa[i] * bb[j];
        }

        float p[4][4];
#pragma unroll
        for (int i = 0; i < 4; ++i) {
            float mi = mrow[i0 + i];
            float li = lrow[i0 + i];
#pragma unroll
            for (int j = 0; j < 4; ++j) {
                float v = s[i][j] * scale;
                if (k0 + j0 + j > q0 + i0 + i) v = NEG_BIG;
                float e = __expf(v - mi) * li;
                p[i][j] = e;
                Ps[(j0 + j) * STRD + (i0 + i)] = e;
            }
        }
        if (write_attn) {
#pragma unroll
            for (int i = 0; i < 4; ++i) {
                float4 pv = make_float4(p[i][0], p[i][1], p[i][2], p[i][3]);
                *(float4*)(attn_base + (size_t)(i0 + i) * SEQ + k0 + j0) = pv;
            }
        }
        __syncthreads();

        // O += P @ V  (thread owns rows i0.., out-cols j0.. reused as d0)
#pragma unroll 8
        for (int j = 0; j < TK; ++j) {
            float4 pj = *(const float4*)&Ps[j * STRD + i0];
            float4 vj = *(const float4*)&Vs[j * STRD + j0];
            float pp[4] = {pj.x, pj.y, pj.z, pj.w};
            float vv[4] = {vj.x, vj.y, vj.z, vj.w};
#pragma unroll
            for (int i = 0; i < 4; ++i)
#pragma unroll
                for (int d = 0; d < 4; ++d) o[i][d] += pp[i] * vv[d];
        }
        __syncthreads();
    }

    // Store O to merged-head layout [b*SEQ + row][h*DK + d]
#pragma unroll
    for (int i = 0; i < 4; ++i) {
        float4 ov = make_float4(o[i][0], o[i][1], o[i][2], o[i][3]);
        *(float4*)(ao + ((size_t)(b * SEQ + q0 + i0 + i)) * DMODEL + h * DK + j0) = ov;
    }
}

// ---------------------------------------------------------------------------
// Launch
// ---------------------------------------------------------------------------
extern "C" void kernel_launch(void* const* d_in, const int* in_sizes, int n_in,
                              void* d_out, int out_size)
{
    const float* Q   = (const float*)d_in[0];
    const float* K   = (const float*)d_in[1];
    const float* V   = (const float*)d_in[2];
    const float* W_q = (const float*)d_in[3];
    const float* W_k = (const float*)d_in[4];
    const float* W_v = (const float*)d_in[5];
    const float* W_o = (const float*)d_in[6];
    const float* b_o = (const float*)d_in[7];
    float* out = (float*)d_out;

    const int write_attn = ((size_t)out_size > OUT_ELEMS) ? 1 : 0;
    float* attn = write_attn ? out + OUT_ELEMS : (float*)0;

    float *gq, *gk, *gv, *gao;
    cudaGetSymbolAddress((void**)&gq,  g_q);
    cudaGetSymbolAddress((void**)&gk,  g_k);
    cudaGetSymbolAddress((void**)&gv,  g_v);
    cudaGetSymbolAddress((void**)&gao, g_ao);

    dim3 ggrid(DMODEL / 128, MROWS / 128);   // (8, 32)
    sgemm_nt<<<ggrid, 256>>>(Q, W_q, gq, (const float*)0, MROWS, DMODEL, DMODEL);
    sgemm_nt<<<ggrid, 256>>>(K, W_k, gk, (const float*)0, MROWS, DMODEL, DMODEL);
    sgemm_nt<<<ggrid, 256>>>(V, W_v, gv, (const float*)0, MROWS, DMODEL, DMODEL);

    cudaFuncSetAttribute(attn_kernel, cudaFuncAttributeMaxDynamicSharedMemorySize,
                         SMEM_ATTN_BYTES);
    dim3 agrid(SEQ / TQ, NHEADS, BATCH);     // (32, 16, 2)
    attn_kernel<<<agrid, 256, SMEM_ATTN_BYTES>>>(gq, gk, gv, attn, gao, write_attn);

    sgemm_nt<<<ggrid, 256>>>(gao, W_o, out, b_o, MROWS, DMODEL, DMODEL);
}

// round 2
// speedup vs baseline: 2.6053x; 2.6053x over previous
#include <cuda_runtime.h>
#include <cuda_bf16.h>
#include <math.h>
#include <stdint.h>

#define BATCH   2
#define SEQ     2048
#define DMODEL  1024
#define NHEADS  16
#define DK      64
#define MROWS   (BATCH * SEQ)                               // 4096
#define OUT_ELEMS   ((size_t)MROWS * DMODEL)                // 4,194,304
#define NEG_BIG (-1.0e30f)

// Scratch (device globals -- no allocation). bf16 hi/lo split copies of q,k,v.
__device__ static __nv_bfloat16 g_qh[MROWS * DMODEL];
__device__ static __nv_bfloat16 g_ql[MROWS * DMODEL];
__device__ static __nv_bfloat16 g_kh[MROWS * DMODEL];
__device__ static __nv_bfloat16 g_kl[MROWS * DMODEL];
__device__ static __nv_bfloat16 g_vh[MROWS * DMODEL];   // transposed per head: [b][h][d][s]
__device__ static __nv_bfloat16 g_vl[MROWS * DMODEL];
__device__ static float         g_ao[MROWS * DMODEL];

// ---------------------------------------------------------------------------
// mma / ldmatrix helpers
// ---------------------------------------------------------------------------
__device__ __forceinline__ uint32_t sptr(const void* p) {
    return (uint32_t)__cvta_generic_to_shared(p);
}
__device__ __forceinline__ void ldsm4(uint32_t& r0, uint32_t& r1, uint32_t& r2,
                                      uint32_t& r3, uint32_t a) {
    asm volatile("ldmatrix.sync.aligned.m8n8.x4.shared.b16 {%0,%1,%2,%3},[%4];"
                 : "=r"(r0), "=r"(r1), "=r"(r2), "=r"(r3) : "r"(a));
}
__device__ __forceinline__ void mma_bf16(float c[4], const uint32_t a[4],
                                         uint32_t b0, uint32_t b1) {
    asm volatile(
        "mma.sync.aligned.m16n8k16.row.col.f32.bf16.bf16.f32 "
        "{%0,%1,%2,%3},{%4,%5,%6,%7},{%8,%9},{%0,%1,%2,%3};"
        : "+f"(c[0]), "+f"(c[1]), "+f"(c[2]), "+f"(c[3])
        : "r"(a[0]), "r"(a[1]), "r"(a[2]), "r"(a[3]), "r"(b0), "r"(b1));
}
__device__ __forceinline__ void split2(float x, __nv_bfloat16& h, __nv_bfloat16& l) {
    h = __float2bfloat16(x);
    l = __float2bfloat16(x - __bfloat162float(h));
}
__device__ __forceinline__ uint32_t pack2(__nv_bfloat16 a, __nv_bfloat16 b) {
    __nv_bfloat162 t; t.x = a; t.y = b;
    return *(uint32_t*)&t;
}

// ---------------------------------------------------------------------------
// GEMM: C[4096,1024] = A @ W^T (+bias).  split-bf16 x3 mma.
// BM=BN=128, BK=32, 256 thr = 8 warps (2M x 4N), warp tile 64x32.
// EPI 0: write bf16 hi/lo in [b][h][s][d] layout (for Q,K)
// EPI 1: write bf16 hi/lo transposed [b][h][d][s] (for V)
// EPI 2: write fp32 + bias to Cout
// ---------------------------------------------------------------------------
#define G_LDS 40            // bf16 smem row stride (32 + 8 pad)
#define G_TILE (128 * G_LDS)
#define SMEM_GEMM_BYTES (8 * G_TILE * 2)   // 4 tiles x 2 buffers x 2B = 81920

template <int EPI>
__global__ __launch_bounds__(256, 1)
void gemm_split(const float* __restrict__ A, const float* __restrict__ W,
                float* __restrict__ Cout, const float* __restrict__ bias,
                __nv_bfloat16* __restrict__ oh, __nv_bfloat16* __restrict__ ol)
{
    extern __shared__ __nv_bfloat16 smg[];
    __nv_bfloat16* sAh = smg;
    __nv_bfloat16* sAl = sAh + 2 * G_TILE;
    __nv_bfloat16* sBh = sAl + 2 * G_TILE;
    __nv_bfloat16* sBl = sBh + 2 * G_TILE;

    const int t  = threadIdx.x;
    const int m0 = blockIdx.y * 128;
    const int n0 = blockIdx.x * 128;
    const int w  = t >> 5, lane = t & 31;
    const int wm = w >> 2, wn = w & 3;          // 2 x 4 warp grid
    const int r0 = t >> 3, c0 = (t & 7) * 4;    // loader: row, col

    float acc[4][4][4];
#pragma unroll
    for (int i = 0; i < 4; ++i)
#pragma unroll
        for (int j = 0; j < 4; ++j)
#pragma unroll
            for (int e = 0; e < 4; ++e) acc[i][j][e] = 0.f;

    float4 ra[4], rb[4];

    auto loadg = [&](int kk) {
#pragma unroll
        for (int i = 0; i < 4; ++i) {
            ra[i] = *(const float4*)(A + (size_t)(m0 + r0 + 32 * i) * DMODEL + kk * 32 + c0);
            rb[i] = *(const float4*)(W + (size_t)(n0 + r0 + 32 * i) * DMODEL + kk * 32 + c0);
        }
    };
    auto stsb = [&](int buf) {
#pragma unroll
        for (int i = 0; i < 4; ++i) {
            int row = r0 + 32 * i;
            __nv_bfloat16 h0, l0, h1, l1, h2, l2, h3, l3;
            split2(ra[i].x, h0, l0); split2(ra[i].y, h1, l1);
            split2(ra[i].z, h2, l2); split2(ra[i].w, h3, l3);
            uint2 uh = make_uint2(pack2(h0, h1), pack2(h2, h3));
            uint2 ul = make_uint2(pack2(l0, l1), pack2(l2, l3));
            *(uint2*)&sAh[buf * G_TILE + row * G_LDS + c0] = uh;
            *(uint2*)&sAl[buf * G_TILE + row * G_LDS + c0] = ul;
            split2(rb[i].x, h0, l0); split2(rb[i].y, h1, l1);
            split2(rb[i].z, h2, l2); split2(rb[i].w, h3, l3);
            uh = make_uint2(pack2(h0, h1), pack2(h2, h3));
            ul = make_uint2(pack2(l0, l1), pack2(l2, l3));
            *(uint2*)&sBh[buf * G_TILE + row * G_LDS + c0] = uh;
            *(uint2*)&sBl[buf * G_TILE + row * G_LDS + c0] = ul;
        }
    };

    const int lm = lane >> 3, lr = lane & 7;

    loadg(0);
    stsb(0);

    const int NK = DMODEL / 32;   // 32 iters
    for (int kk = 0; kk < NK; ++kk) {
        __syncthreads();
        if (kk + 1 < NK) loadg(kk + 1);
        const int buf = kk & 1;
#pragma unroll
        for (int k16 = 0; k16 < 32; k16 += 16) {
            uint32_t ah[4][4], al[4][4], bh[4][2], bl[4][2];
#pragma unroll
            for (int mt = 0; mt < 4; ++mt) {
                int row = wm * 64 + mt * 16 + lr + 8 * (lm & 1);
                int col = k16 + 8 * (lm >> 1);
                ldsm4(ah[mt][0], ah[mt][1], ah[mt][2], ah[mt][3],
                      sptr(&sAh[buf * G_TILE + row * G_LDS + col]));
                ldsm4(al[mt][0], al[mt][1], al[mt][2], al[mt][3],
                      sptr(&sAl[buf * G_TILE + row * G_LDS + col]));
            }
#pragma unroll
            for (int g = 0; g < 2; ++g) {
                int row = wn * 32 + g * 16 + 8 * (lm >> 1) + lr;
                int col = k16 + 8 * (lm & 1);
                ldsm4(bh[2 * g][0], bh[2 * g][1], bh[2 * g + 1][0], bh[2 * g + 1][1],
                      sptr(&sBh[buf * G_TILE + row * G_LDS + col]));
                ldsm4(bl[2 * g][0], bl[2 * g][1], bl[2 * g + 1][0], bl[2 * g + 1][1],
                      sptr(&sBl[buf * G_TILE + row * G_LDS + col]));
            }
#pragma unroll
            for (int mt = 0; mt < 4; ++mt)
#pragma unroll
                for (int nt = 0; nt < 4; ++nt) {
                    mma_bf16(acc[mt][nt], ah[mt], bh[nt][0], bh[nt][1]);
                    mma_bf16(acc[mt][nt], ah[mt], bl[nt][0], bl[nt][1]);
                    mma_bf16(acc[mt][nt], al[mt], bh[nt][0], bh[nt][1]);
                }
        }
        if (kk + 1 < NK) stsb((kk + 1) & 1);
    }

    // Epilogue
    const int cr = lane >> 2, cc = lane & 3;
#pragma unroll
    for (int mt = 0; mt < 4; ++mt)
#pragma unroll
        for (int nt = 0; nt < 4; ++nt) {
#pragma unroll
            for (int half = 0; half < 2; ++half) {
                int gm = m0 + wm * 64 + mt * 16 + cr + 8 * half;
                int gn = n0 + wn * 32 + nt * 8 + 2 * cc;
                float v0 = acc[mt][nt][2 * half + 0];
                float v1 = acc[mt][nt][2 * half + 1];
                if (EPI == 2) {
                    float2 o = make_float2(v0 + bias[gn], v1 + bias[gn + 1]);
                    *(float2*)(Cout + (size_t)gm * DMODEL + gn) = o;
                } else {
                    int b = gm >> 11, s = gm & 2047, h = gn >> 6, d = gn & 63;
                    __nv_bfloat16 h0, l0, h1, l1;
                    split2(v0, h0, l0); split2(v1, h1, l1);
                    if (EPI == 0) {
                        size_t idx = (((size_t)(b * NHEADS + h) * SEQ) + s) * DK + d;
                        *(uint32_t*)(oh + idx) = pack2(h0, h1);
                        *(uint32_t*)(ol + idx) = pack2(l0, l1);
                    } else {
                        size_t idx = (((size_t)(b * NHEADS + h) * DK) + d) * SEQ + s;
                        oh[idx] = h0; ol[idx] = l0;
                        oh[idx + SEQ] = h1; ol[idx + SEQ] = l1;
                    }
                }
            }
        }
}

// ---------------------------------------------------------------------------
// Attention: per (q-tile 64, h, b). Two-pass flash + full attn write.
// 256 thr = 8 warps (4M x 2N); warp tile 16x32. split-bf16 x3 mma.
// ---------------------------------------------------------------------------
#define A_LDS 72   // bf16 row stride (64 + 8)
#define A_TILE (64 * A_LDS)
#define PS_LDS 68
#define SMEM_ATTN_BYTES (8 * A_TILE * 2 + 64 * PS_LDS * 4 + 2 * 64 * 4)

__global__ __launch_bounds__(256, 1)
void attn_split(const __nv_bfloat16* __restrict__ qh, const __nv_bfloat16* __restrict__ ql,
                const __nv_bfloat16* __restrict__ kh, const __nv_bfloat16* __restrict__ kl,
                const __nv_bfloat16* __restrict__ vh, const __nv_bfloat16* __restrict__ vl,
                float* __restrict__ attn, float* __restrict__ ao, int write_attn)
{
    extern __shared__ __nv_bfloat16 sma[];
    __nv_bfloat16* Qh = sma;
    __nv_bfloat16* Ql = Qh + A_TILE;
    __nv_bfloat16* Kh = Ql + A_TILE;
    __nv_bfloat16* Kl = Kh + A_TILE;
    __nv_bfloat16* Vh = Kl + A_TILE;
    __nv_bfloat16* Vl = Vh + A_TILE;
    __nv_bfloat16* Ph = Vl + A_TILE;
    __nv_bfloat16* Pl = Ph + A_TILE;
    float* Ps   = (float*)(Pl + A_TILE);
    float* mrow = Ps + 64 * PS_LDS;
    float* lrow = mrow + 64;

    const int qt = blockIdx.x, h = blockIdx.y, b = blockIdx.z;
    const int q0 = qt * 64;
    const int t = threadIdx.x, w = t >> 5, lane = t & 31;
    const int wm = w >> 1, wn = w & 1;           // 4 x 2 warp grid
    const int lm = lane >> 3, lr = lane & 7;     // ldmatrix lane decode
    const int cr = lane >> 2, cc = lane & 3;     // mma C decode
    const float scale = 0.125f;

    const size_t bh = (size_t)(b * NHEADS + h);
    const __nv_bfloat16* qbh = qh + bh * SEQ * DK;
    const __nv_bfloat16* qbl = ql + bh * SEQ * DK;
    const __nv_bfloat16* kbh = kh + bh * SEQ * DK;
    const __nv_bfloat16* kbl = kl + bh * SEQ * DK;
    const __nv_bfloat16* vbh = vh + bh * DK * SEQ;
    const __nv_bfloat16* vbl = vl + bh * DK * SEQ;

    const int trow = t >> 2, tsg = t & 3;
    auto cp_tile = [&](__nv_bfloat16* dst, const __nv_bfloat16* src, int rstride) {
        const int4* s = (const int4*)(src + (size_t)trow * rstride + tsg * 16);
        int4* d = (int4*)(dst + trow * A_LDS + tsg * 16);
        d[0] = s[0]; d[1] = s[1];
    };

    // load Q tile once
    cp_tile(Qh, qbh + (size_t)q0 * DK, DK);
    cp_tile(Ql, qbl + (size_t)q0 * DK, DK);
    if (t < 64) { mrow[t] = NEG_BIG; lrow[t] = 0.f; }
    __syncthreads();

    // QK^T mma for one 64x64 tile -> s[nt][4]
    auto qk_mma = [&](float s[4][4]) {
#pragma unroll
        for (int nt = 0; nt < 4; ++nt)
#pragma unroll
            for (int e = 0; e < 4; ++e) s[nt][e] = 0.f;
#pragma unroll
        for (int kc = 0; kc < 4; ++kc) {
            uint32_t ahf[4], alf[4], bhf[4][2], blf[4][2];
            {
                int row = wm * 16 + lr + 8 * (lm & 1);
                int col = kc * 16 + 8 * (lm >> 1);
                ldsm4(ahf[0], ahf[1], ahf[2], ahf[3], sptr(&Qh[row * A_LDS + col]));
                ldsm4(alf[0], alf[1], alf[2], alf[3], sptr(&Ql[row * A_LDS + col]));
            }
#pragma unroll
            for (int g = 0; g < 2; ++g) {
                int row = wn * 32 + g * 16 + 8 * (lm >> 1) + lr;
                int col = kc * 16 + 8 * (lm & 1);
                ldsm4(bhf[2 * g][0], bhf[2 * g][1], bhf[2 * g + 1][0], bhf[2 * g + 1][1],
                      sptr(&Kh[row * A_LDS + col]));
                ldsm4(blf[2 * g][0], blf[2 * g][1], blf[2 * g + 1][0], blf[2 * g + 1][1],
                      sptr(&Kl[row * A_LDS + col]));
            }
#pragma unroll
            for (int nt = 0; nt < 4; ++nt) {
                mma_bf16(s[nt], ahf, bhf[nt][0], bhf[nt][1]);
                mma_bf16(s[nt], ahf, blf[nt][0], blf[nt][1]);
                mma_bf16(s[nt], alf, bhf[nt][0], bhf[nt][1]);
            }
        }
    };

    // ---------------- Pass 1 ----------------
    for (int kt = 0; kt <= qt; ++kt) {
        const int k0 = kt * 64;
        cp_tile(Kh, kbh + (size_t)k0 * DK, DK);
        cp_tile(Kl, kbl + (size_t)k0 * DK, DK);
        __syncthreads();

        float s[4][4];
        qk_mma(s);

#pragma unroll
        for (int nt = 0; nt < 4; ++nt)
#pragma unroll
            for (int half = 0; half < 2; ++half) {
                int i = wm * 16 + cr + 8 * half;
                int j = wn * 32 + nt * 8 + 2 * cc;
                float v0 = s[nt][2 * half] * scale;
                float v1 = s[nt][2 * half + 1] * scale;
                if (k0 + j > q0 + i) v0 = NEG_BIG;
                if (k0 + j + 1 > q0 + i) v1 = NEG_BIG;
                *(float2*)&Ps[i * PS_LDS + j] = make_float2(v0, v1);
            }
        __syncthreads();

        {
            int row = t >> 2, sub = t & 3;
            float m = NEG_BIG;
#pragma unroll
            for (int u = 0; u < 16; ++u) m = fmaxf(m, Ps[row * PS_LDS + sub + 4 * u]);
            m = fmaxf(m, __shfl_xor_sync(0xffffffff, m, 1));
            m = fmaxf(m, __shfl_xor_sync(0xffffffff, m, 2));
            float mold = mrow[row];
            float tm = fmaxf(mold, m);
            float sum = 0.f;
#pragma unroll
            for (int u = 0; u < 16; ++u) sum += __expf(Ps[row * PS_LDS + sub + 4 * u] - tm);
            sum += __shfl_xor_sync(0xffffffff, sum, 1);
            sum += __shfl_xor_sync(0xffffffff, sum, 2);
            if (sub == 0) { lrow[row] = lrow[row] * __expf(mold - tm) + sum; mrow[row] = tm; }
        }
        __syncthreads();
    }
    if (t < 64) lrow[t] = 1.0f / lrow[t];
    __syncthreads();

    // ---------------- Pass 2 ----------------
    float o[4][4];
#pragma unroll
    for (int nt = 0; nt < 4; ++nt)
#pragma unroll
        for (int e = 0; e < 4; ++e) o[nt][e] = 0.f;

    float* attn_base = write_attn ? attn + (bh * SEQ + q0) * SEQ : (float*)0;

    for (int kt = 0; kt < SEQ / 64; ++kt) {
        const int k0 = kt * 64;
        if (kt > qt) {
            if (write_attn) {
                float4 z = make_float4(0.f, 0.f, 0.f, 0.f);
                float* dst = attn_base + (size_t)trow * SEQ + k0 + tsg * 16;
                *(float4*)(dst) = z; *(float4*)(dst + 4) = z;
                *(float4*)(dst + 8) = z; *(float4*)(dst + 12) = z;
            }
            continue;
        }
        cp_tile(Kh, kbh + (size_t)k0 * DK, DK);
        cp_tile(Kl, kbl + (size_t)k0 * DK, DK);
        cp_tile(Vh, vbh + k0, SEQ);
        cp_tile(Vl, vbl + k0, SEQ);
        __syncthreads();

        float s[4][4];
        qk_mma(s);

        float mi0 = mrow[wm * 16 + cr], mi1 = mrow[wm * 16 + cr + 8];
        float li0 = lrow[wm * 16 + cr], li1 = lrow[wm * 16 + cr + 8];
#pragma unroll
        for (int nt = 0; nt < 4; ++nt)
#pragma unroll
            for (int half = 0; half < 2; ++half) {
                int i = wm * 16 + cr + 8 * half;
                int j = wn * 32 + nt * 8 + 2 * cc;
                float mi = half ? mi1 : mi0;
                float li = half ? li1 : li0;
                float v0 = s[nt][2 * half] * scale;
                float v1 = s[nt][2 * half + 1] * scale;
                if (k0 + j > q0 + i) v0 = NEG_BIG;
                if (k0 + j + 1 > q0 + i) v1 = NEG_BIG;
                float p0 = __expf(v0 - mi) * li;
                float p1 = __expf(v1 - mi) * li;
                if (write_attn)
                    *(float2*)(attn_base + (size_t)i * SEQ + k0 + j) = make_float2(p0, p1);
                __nv_bfloat16 ph0, pl0, ph1, pl1;
                split2(p0, ph0, pl0); split2(p1, ph1, pl1);
                *(uint32_t*)&Ph[i * A_LDS + j] = pack2(ph0, ph1);
                *(uint32_t*)&Pl[i * A_LDS + j] = pack2(pl0, pl1);
            }
        __syncthreads();

        // O += P @ V   (A = P[i][j], B = Vt[d][j] col-major)
#pragma unroll
        for (int kc = 0; kc < 4; ++kc) {
            uint32_t ahf[4], alf[4], bhf[4][2], blf[4][2];
            {
                int row = wm * 16 + lr + 8 * (lm & 1);
                int col = kc * 16 + 8 * (lm >> 1);
                ldsm4(ahf[0], ahf[1], ahf[2], ahf[3], sptr(&Ph[row * A_LDS + col]));
                ldsm4(alf[0], alf[1], alf[2], alf[3], sptr(&Pl[row * A_LDS + col]));
            }
#pragma unroll
            for (int g = 0; g < 2; ++g) {
                int row = wn * 32 + g * 16 + 8 * (lm >> 1) + lr;
                int col = kc * 16 + 8 * (lm & 1);
                ldsm4(bhf[2 * g][0], bhf[2 * g][1], bhf[2 * g + 1][0], bhf[2 * g + 1][1],
                      sptr(&Vh[row * A_LDS + col]));
                ldsm4(blf[2 * g][0], blf[2 * g][1], blf[2 * g + 1][0], blf[2 * g + 1][1],
                      sptr(&Vl[row * A_LDS + col]));
            }
#pragma unroll
            for (int nt = 0; nt < 4; ++nt) {
                mma_bf16(o[nt], ahf, bhf[nt][0], bhf[nt][1]);
                mma_bf16(o[nt], ahf, blf[nt][0], blf[nt][1]);
                mma_bf16(o[nt], alf, bhf[nt][0], bhf[nt][1]);
            }
        }
        __syncthreads();
    }

    // store O (merged-head fp32 layout for the W_o GEMM)
#pragma unroll
    for (int nt = 0; nt < 4; ++nt)
#pragma unroll
        for (int half = 0; half < 2; ++half) {
            int i = wm * 16 + cr + 8 * half;
            int d = wn * 32 + nt * 8 + 2 * cc;
            float2 ov = make_float2(o[nt][2 * half], o[nt][2 * half + 1]);
            *(float2*)(ao + (size_t)(b * SEQ + q0 + i) * DMODEL + h * DK + d) = ov;
        }
}

// ---------------------------------------------------------------------------
// Launch
// ---------------------------------------------------------------------------
extern "C" void kernel_launch(void* const* d_in, const int* in_sizes, int n_in,
                              void* d_out, int out_size)
{
    const float* Q   = (const float*)d_in[0];
    const float* K   = (const float*)d_in[1];
    const float* V   = (const float*)d_in[2];
    const float* W_q = (const float*)d_in[3];
    const float* W_k = (const float*)d_in[4];
    const float* W_v = (const float*)d_in[5];
    const float* W_o = (const float*)d_in[6];
    const float* b_o = (const float*)d_in[7];
    float* out = (float*)d_out;

    const int write_attn = ((size_t)out_size > OUT_ELEMS) ? 1 : 0;
    float* attn = write_attn ? out + OUT_ELEMS : (float*)0;

    __nv_bfloat16 *qh, *ql, *kh, *kl, *vh, *vl; float* ao;
    cudaGetSymbolAddress((void**)&qh, g_qh);
    cudaGetSymbolAddress((void**)&ql, g_ql);
    cudaGetSymbolAddress((void**)&kh, g_kh);
    cudaGetSymbolAddress((void**)&kl, g_kl);
    cudaGetSymbolAddress((void**)&vh, g_vh);
    cudaGetSymbolAddress((void**)&vl, g_vl);
    cudaGetSymbolAddress((void**)&ao, g_ao);

    cudaFuncSetAttribute(gemm_split<0>, cudaFuncAttributeMaxDynamicSharedMemorySize, SMEM_GEMM_BYTES);
    cudaFuncSetAttribute(gemm_split<1>, cudaFuncAttributeMaxDynamicSharedMemorySize, SMEM_GEMM_BYTES);
    cudaFuncSetAttribute(gemm_split<2>, cudaFuncAttributeMaxDynamicSharedMemorySize, SMEM_GEMM_BYTES);
    cudaFuncSetAttribute(attn_split,    cudaFuncAttributeMaxDynamicSharedMemorySize, SMEM_ATTN_BYTES);

    dim3 ggrid(DMODEL / 128, MROWS / 128);   // (8, 32)
    gemm_split<0><<<ggrid, 256, SMEM_GEMM_BYTES>>>(Q, W_q, (float*)0, (const float*)0, qh, ql);
    gemm_split<0><<<ggrid, 256, SMEM_GEMM_BYTES>>>(K, W_k, (float*)0, (const float*)0, kh, kl);
    gemm_split<1><<<ggrid, 256, SMEM_GEMM_BYTES>>>(V, W_v, (float*)0, (const float*)0, vh, vl);

    dim3 agrid(SEQ / 64, NHEADS, BATCH);     // (32, 16, 2)
    attn_split<<<agrid, 256, SMEM_ATTN_BYTES>>>(qh, ql, kh, kl, vh, vl, attn, ao, write_attn);

    gemm_split<2><<<ggrid, 256, SMEM_GEMM_BYTES>>>(ao, W_o, out, b_o,
                                                   (__nv_bfloat16*)0, (__nv_bfloat16*)0);
}

// round 3
// speedup vs baseline: 2.6359x; 1.0117x over previous
#include <cuda_runtime.h>
#include <cuda_bf16.h>
#include <stdint.h>

#define BATCH   2
#define SEQ     2048
#define DMODEL  1024
#define NHEADS  16
#define DK      64
#define MROWS   (BATCH * SEQ)                      // 4096
#define OUT_ELEMS ((size_t)MROWS * DMODEL)
#define NEG_BIG (-1.0e30f)

typedef __nv_bfloat16 bf16;

// ---------------- scratch (device globals) ----------------
__device__ static bf16 g_xh[MROWS * DMODEL],  g_xl[MROWS * DMODEL];   // pre-split input
__device__ static bf16 g_wh[DMODEL * DMODEL], g_wl[DMODEL * DMODEL];  // pre-split weight
__device__ static bf16 g_qh[MROWS * DMODEL],  g_ql[MROWS * DMODEL];
__device__ static bf16 g_kh[MROWS * DMODEL],  g_kl[MROWS * DMODEL];
__device__ static bf16 g_vh[MROWS * DMODEL],  g_vl[MROWS * DMODEL];   // [b][h][d][s]
__device__ static bf16 g_aoh[MROWS * DMODEL], g_aol[MROWS * DMODEL];

// ---------------- helpers ----------------
__device__ __forceinline__ uint32_t sptr(const void* p) {
    return (uint32_t)__cvta_generic_to_shared(p);
}
__device__ __forceinline__ void ldsm4(uint32_t& r0, uint32_t& r1, uint32_t& r2,
                                      uint32_t& r3, uint32_t a) {
    asm volatile("ldmatrix.sync.aligned.m8n8.x4.shared.b16 {%0,%1,%2,%3},[%4];"
                 : "=r"(r0), "=r"(r1), "=r"(r2), "=r"(r3) : "r"(a));
}
__device__ __forceinline__ void mma_bf16(float c[4], const uint32_t a[4],
                                         uint32_t b0, uint32_t b1) {
    asm volatile(
        "mma.sync.aligned.m16n8k16.row.col.f32.bf16.bf16.f32 "
        "{%0,%1,%2,%3},{%4,%5,%6,%7},{%8,%9},{%0,%1,%2,%3};"
        : "+f"(c[0]), "+f"(c[1]), "+f"(c[2]), "+f"(c[3])
        : "r"(a[0]), "r"(a[1]), "r"(a[2]), "r"(a[3]), "r"(b0), "r"(b1));
}
__device__ __forceinline__ void split2(float x, bf16& h, bf16& l) {
    h = __float2bfloat16(x);
    l = __float2bfloat16(x - __bfloat162float(h));
}
__device__ __forceinline__ uint32_t pack2(bf16 a, bf16 b) {
    __nv_bfloat162 t; t.x = a; t.y = b;
    return *(uint32_t*)&t;
}
__device__ __forceinline__ void cpa16(void* dst, const void* src) {
    asm volatile("cp.async.cg.shared.global [%0],[%1],16;"
                 :: "r"(sptr(dst)), "l"(__cvta_generic_to_global(src)));
}
#define CP_COMMIT  asm volatile("cp.async.commit_group;")
#define CP_WAIT0   asm volatile("cp.async.wait_group 0;")

// ---------------- split kernel: fp32 -> bf16 hi/lo ----------------
__global__ __launch_bounds__(256)
void split_kernel(const float* __restrict__ in, bf16* __restrict__ oh,
                  bf16* __restrict__ ol, int n4)
{
    int i = blockIdx.x * blockDim.x + threadIdx.x;
    if (i >= n4) return;
    float4 v = ((const float4*)in)[i];
    bf16 h0, l0, h1, l1, h2, l2, h3, l3;
    split2(v.x, h0, l0); split2(v.y, h1, l1);
    split2(v.z, h2, l2); split2(v.w, h3, l3);
    ((uint2*)oh)[i] = make_uint2(pack2(h0, h1), pack2(h2, h3));
    ((uint2*)ol)[i] = make_uint2(pack2(l0, l1), pack2(l2, l3));
}

// ---------------------------------------------------------------------------
// GEMM: C[4096,1024] = A @ B^T, A/B pre-split bf16. 128x128x32, 8 warps 2x4.
// EPI 0: bf16 hi/lo out [b][h][s][d];  EPI 1: transposed [b][h][d][s];
// EPI 2: fp32 + bias.
// ---------------------------------------------------------------------------
#define G_LDS 40
#define G_TILE (128 * G_LDS)
#define SMEM_GEMM_BYTES (8 * G_TILE * 2)     // 81920

template <int EPI>
__global__ __launch_bounds__(256)
void gemm_bf16(const bf16* __restrict__ Ah, const bf16* __restrict__ Al,
               const bf16* __restrict__ Bh, const bf16* __restrict__ Bl,
               float* __restrict__ Cout, const float* __restrict__ bias,
               bf16* __restrict__ oh, bf16* __restrict__ ol)
{
    extern __shared__ bf16 smg[];
    const int t = threadIdx.x;
    const int m0 = blockIdx.y * 128, n0 = blockIdx.x * 128;
    const int w = t >> 5, lane = t & 31;
    const int wm = w >> 2, wn = w & 3;
    const int lm = lane >> 3, lr = lane & 7;

    float acc[4][4][4];
#pragma unroll
    for (int i = 0; i < 4; ++i)
#pragma unroll
        for (int j = 0; j < 4; ++j)
#pragma unroll
            for (int e = 0; e < 4; ++e) acc[i][j][e] = 0.f;

    auto issue = [&](int kk) {
        bf16* d = smg + (kk & 1) * 4 * G_TILE;
        const bf16* srcs[4] = {
            Ah + (size_t)m0 * DMODEL + kk * 32, Al + (size_t)m0 * DMODEL + kk * 32,
            Bh + (size_t)n0 * DMODEL + kk * 32, Bl + (size_t)n0 * DMODEL + kk * 32};
        const int r = t >> 2, o = (t & 3) * 8;
#pragma unroll
        for (int tl = 0; tl < 4; ++tl) {
            cpa16(d + tl * G_TILE + r * G_LDS + o,        srcs[tl] + (size_t)r * DMODEL + o);
            cpa16(d + tl * G_TILE + (r + 64) * G_LDS + o, srcs[tl] + (size_t)(r + 64) * DMODEL + o);
        }
    };

    issue(0); CP_COMMIT;

    const int NK = DMODEL / 32;
    for (int kk = 0; kk < NK; ++kk) {
        CP_WAIT0;
        __syncthreads();
        if (kk + 1 < NK) { issue(kk + 1); CP_COMMIT; }
        const bf16* sAh = smg + (kk & 1) * 4 * G_TILE;
        const bf16* sAl = sAh + G_TILE;
        const bf16* sBh = sAl + G_TILE;
        const bf16* sBl = sBh + G_TILE;
#pragma unroll
        for (int k16 = 0; k16 < 32; k16 += 16) {
            uint32_t ah[4][4], al[4][4], bh[4][2], bl[4][2];
#pragma unroll
            for (int mt = 0; mt < 4; ++mt) {
                int row = wm * 64 + mt * 16 + lr + 8 * (lm & 1);
                int col = k16 + 8 * (lm >> 1);
                ldsm4(ah[mt][0], ah[mt][1], ah[mt][2], ah[mt][3], sptr(&sAh[row * G_LDS + col]));
                ldsm4(al[mt][0], al[mt][1], al[mt][2], al[mt][3], sptr(&sAl[row * G_LDS + col]));
            }
#pragma unroll
            for (int g = 0; g < 2; ++g) {
                int row = wn * 32 + g * 16 + 8 * (lm >> 1) + lr;
                int col = k16 + 8 * (lm & 1);
                ldsm4(bh[2 * g][0], bh[2 * g][1], bh[2 * g + 1][0], bh[2 * g + 1][1],
                      sptr(&sBh[row * G_LDS + col]));
                ldsm4(bl[2 * g][0], bl[2 * g][1], bl[2 * g + 1][0], bl[2 * g + 1][1],
                      sptr(&sBl[row * G_LDS + col]));
            }
#pragma unroll
            for (int mt = 0; mt < 4; ++mt)
#pragma unroll
                for (int nt = 0; nt < 4; ++nt) {
                    mma_bf16(acc[mt][nt], ah[mt], bh[nt][0], bh[nt][1]);
                    mma_bf16(acc[mt][nt], ah[mt], bl[nt][0], bl[nt][1]);
                    mma_bf16(acc[mt][nt], al[mt], bh[nt][0], bh[nt][1]);
                }
        }
    }

    const int cr = lane >> 2, cc = lane & 3;
#pragma unroll
    for (int mt = 0; mt < 4; ++mt)
#pragma unroll
        for (int nt = 0; nt < 4; ++nt)
#pragma unroll
            for (int half = 0; half < 2; ++half) {
                int gm = m0 + wm * 64 + mt * 16 + cr + 8 * half;
                int gn = n0 + wn * 32 + nt * 8 + 2 * cc;
                float v0 = acc[mt][nt][2 * half + 0];
                float v1 = acc[mt][nt][2 * half + 1];
                if (EPI == 2) {
                    *(float2*)(Cout + (size_t)gm * DMODEL + gn) =
                        make_float2(v0 + bias[gn], v1 + bias[gn + 1]);
                } else {
                    int b = gm >> 11, s = gm & 2047, h = gn >> 6, d = gn & 63;
                    bf16 h0, l0, h1, l1;
                    split2(v0, h0, l0); split2(v1, h1, l1);
                    if (EPI == 0) {
                        size_t idx = (((size_t)(b * NHEADS + h) * SEQ) + s) * DK + d;
                        *(uint32_t*)(oh + idx) = pack2(h0, h1);
                        *(uint32_t*)(ol + idx) = pack2(l0, l1);
                    } else {
                        size_t idx = (((size_t)(b * NHEADS + h) * DK) + d) * SEQ + s;
                        oh[idx] = h0; ol[idx] = l0;
                        oh[idx + SEQ] = h1; ol[idx + SEQ] = l1;
                    }
                }
            }
}

// ---------------------------------------------------------------------------
// Attention: per (q-tile 64, h, b). Fragment softmax + cp.async double buffer.
// 8 warps (4M x 2N), warp tile 16x32.
// ---------------------------------------------------------------------------
#define A_LDS 72
#define A_TILE (64 * A_LDS)
#define SMEM_ATTN_BYTES (12 * A_TILE * 2 + 2 * 256 * 4 + 2 * 64 * 4)   // 113152

__global__ __launch_bounds__(256)
void attn_split(const bf16* __restrict__ qh, const bf16* __restrict__ ql,
                const bf16* __restrict__ kh, const bf16* __restrict__ kl,
                const bf16* __restrict__ vh, const bf16* __restrict__ vl,
                float* __restrict__ attn, bf16* __restrict__ aoh,
                bf16* __restrict__ aol, int write_attn)
{
    extern __shared__ bf16 sma[];
    bf16* Qh = sma;
    bf16* Ql = sma + A_TILE;
    bf16* KhB[2] = {sma + 2 * A_TILE, sma + 3 * A_TILE};
    bf16* KlB[2] = {sma + 4 * A_TILE, sma + 5 * A_TILE};
    bf16* VhB[2] = {sma + 6 * A_TILE, sma + 7 * A_TILE};
    bf16* VlB[2] = {sma + 8 * A_TILE, sma + 9 * A_TILE};
    bf16* Ph = sma + 10 * A_TILE;
    bf16* Pl = sma + 11 * A_TILE;
    float* pm   = (float*)(sma + 12 * A_TILE);   // [par][wn][64]
    float* plx  = pm + 256;
    float* mrow = plx + 256;
    float* lrow = mrow + 64;

    const int qt = blockIdx.x, h = blockIdx.y, b = blockIdx.z;
    const int q0 = qt * 64;
    const int t = threadIdx.x, w = t >> 5, lane = t & 31;
    const int wm = w >> 1, wn = w & 1;
    const int lm = lane >> 3, lr = lane & 7;
    const int cr = lane >> 2, cc = lane & 3;
    const float scale = 0.125f;

    const size_t bh = (size_t)(b * NHEADS + h);
    const bf16* qbh = qh + bh * SEQ * DK;
    const bf16* qbl = ql + bh * SEQ * DK;
    const bf16* kbh = kh + bh * SEQ * DK;
    const bf16* kbl = kl + bh * SEQ * DK;
    const bf16* vbh = vh + bh * DK * SEQ;
    const bf16* vbl = vl + bh * DK * SEQ;

    auto cpa_tile = [&](bf16* dst, const bf16* src, int rstride) {
        const int r = t >> 3, o = (t & 7) * 8;
        cpa16(dst + r * A_LDS + o,        src + (size_t)r * rstride + o);
        cpa16(dst + (r + 32) * A_LDS + o, src + (size_t)(r + 32) * rstride + o);
    };

    auto qk_mma = [&](float s[4][4], const bf16* KH, const bf16* KL) {
#pragma unroll
        for (int nt = 0; nt < 4; ++nt)
#pragma unroll
            for (int e = 0; e < 4; ++e) s[nt][e] = 0.f;
#pragma unroll
        for (int kc = 0; kc < 4; ++kc) {
            uint32_t af[4], alf[4], bf[4][2], blf[4][2];
            {
                int row = wm * 16 + lr + 8 * (lm & 1);
                int col = kc * 16 + 8 * (lm >> 1);
                ldsm4(af[0], af[1], af[2], af[3], sptr(&Qh[row * A_LDS + col]));
                ldsm4(alf[0], alf[1], alf[2], alf[3], sptr(&Ql[row * A_LDS + col]));
            }
#pragma unroll
            for (int g = 0; g < 2; ++g) {
                int row = wn * 32 + g * 16 + 8 * (lm >> 1) + lr;
                int col = kc * 16 + 8 * (lm & 1);
                ldsm4(bf[2 * g][0], bf[2 * g][1], bf[2 * g + 1][0], bf[2 * g + 1][1],
                      sptr(&KH[row * A_LDS + col]));
                ldsm4(blf[2 * g][0], blf[2 * g][1], blf[2 * g + 1][0], blf[2 * g + 1][1],
                      sptr(&KL[row * A_LDS + col]));
            }
#pragma unroll
            for (int nt = 0; nt < 4; ++nt) {
                mma_bf16(s[nt], af, bf[nt][0], bf[nt][1]);
                mma_bf16(s[nt], af, blf[nt][0], blf[nt][1]);
                mma_bf16(s[nt], alf, bf[nt][0], bf[nt][1]);
            }
        }
    };

    // prologue: Q + K(0)
    cpa_tile(Qh, qbh + (size_t)q0 * DK, DK);
    cpa_tile(Ql, qbl + (size_t)q0 * DK, DK);
    cpa_tile(KhB[0], kbh, DK);
    cpa_tile(KlB[0], kbl, DK);
    CP_COMMIT;
    if (t < 64) { mrow[t] = NEG_BIG; lrow[t] = 0.f; }

    // ---------------- Pass 1: fragment softmax stats ----------------
    for (int kt = 0; kt <= qt; ++kt) {
        CP_WAIT0;
        __syncthreads();
        if (kt + 1 <= qt) {
            cpa_tile(KhB[(kt + 1) & 1], kbh + (size_t)(kt + 1) * 64 * DK, DK);
            cpa_tile(KlB[(kt + 1) & 1], kbl + (size_t)(kt + 1) * 64 * DK, DK);
            CP_COMMIT;
        }
        const int k0 = kt * 64;
        float s[4][4];
        qk_mma(s, KhB[kt & 1], KlB[kt & 1]);

        float vv[4][4];
        float mx0 = NEG_BIG, mx1 = NEG_BIG;
#pragma unroll
        for (int nt = 0; nt < 4; ++nt)
#pragma unroll
            for (int e = 0; e < 4; ++e) {
                int rg = q0 + wm * 16 + cr + 8 * (e >> 1);
                int jg = k0 + wn * 32 + nt * 8 + 2 * cc + (e & 1);
                float v = s[nt][e] * scale;
                if (jg > rg) v = NEG_BIG;
                vv[nt][e] = v;
                if (e >> 1) mx1 = fmaxf(mx1, v); else mx0 = fmaxf(mx0, v);
            }
        mx0 = fmaxf(mx0, __shfl_xor_sync(0xffffffff, mx0, 1));
        mx0 = fmaxf(mx0, __shfl_xor_sync(0xffffffff, mx0, 2));
        mx1 = fmaxf(mx1, __shfl_xor_sync(0xffffffff, mx1, 1));
        mx1 = fmaxf(mx1, __shfl_xor_sync(0xffffffff, mx1, 2));
        float s0 = 0.f, s1 = 0.f;
#pragma unroll
        for (int nt = 0; nt < 4; ++nt)
#pragma unroll
            for (int e = 0; e < 4; ++e) {
                float ev = __expf(vv[nt][e] - ((e >> 1) ? mx1 : mx0));
                if (e >> 1) s1 += ev; else s0 += ev;
            }
        s0 += __shfl_xor_sync(0xffffffff, s0, 1);
        s0 += __shfl_xor_sync(0xffffffff, s0, 2);
        s1 += __shfl_xor_sync(0xffffffff, s1, 1);
        s1 += __shfl_xor_sync(0xffffffff, s1, 2);
        const int par = kt & 1;
        if ((lane & 3) == 0) {
            int base = (par * 2 + wn) * 64 + wm * 16 + cr;
            pm[base]      = mx0;  plx[base]      = s0;
            pm[base + 8]  = mx1;  plx[base + 8]  = s1;
        }
        __syncthreads();
        if (t < 64) {
            float m0 = pm[(par * 2 + 0) * 64 + t], m1 = pm[(par * 2 + 1) * 64 + t];
            float l0 = plx[(par * 2 + 0) * 64 + t], l1 = plx[(par * 2 + 1) * 64 + t];
            float mo = mrow[t];
            float mn = fmaxf(mo, fmaxf(m0, m1));
            lrow[t] = lrow[t] * __expf(mo - mn) + l0 * __expf(m0 - mn) + l1 * __expf(m1 - mn);
            mrow[t] = mn;
        }
    }
    if (t < 64) lrow[t] = 1.0f / lrow[t];

    // prologue for pass 2: K(0), V(0)
    cpa_tile(KhB[0], kbh, DK);
    cpa_tile(KlB[0], kbl, DK);
    cpa_tile(VhB[0], vbh, SEQ);
    cpa_tile(VlB[0], vbl, SEQ);
    CP_COMMIT;

    float* attn_base = write_attn ? attn + (bh * SEQ + q0) * SEQ : (float*)0;
    // zero-fill fully-masked tiles (overlaps with cp.async)
    if (write_attn) {
        const int zr = t >> 2, zc = (t & 3) * 16;
        for (int kt = qt + 1; kt < SEQ / 64; ++kt) {
            float4 z = make_float4(0.f, 0.f, 0.f, 0.f);
            float* dst = attn_base + (size_t)zr * SEQ + kt * 64 + zc;
            *(float4*)(dst) = z; *(float4*)(dst + 4) = z;
            *(float4*)(dst + 8) = z; *(float4*)(dst + 12) = z;
        }
    }
    __syncthreads();

    // ---------------- Pass 2: attn write + P@V ----------------
    float o[4][4];
#pragma unroll
    for (int nt = 0; nt < 4; ++nt)
#pragma unroll
        for (int e = 0; e < 4; ++e) o[nt][e] = 0.f;

    for (int kt = 0; kt <= qt; ++kt) {
        CP_WAIT0;
        __syncthreads();
        if (kt + 1 <= qt) {
            cpa_tile(KhB[(kt + 1) & 1], kbh + (size_t)(kt + 1) * 64 * DK, DK);
            cpa_tile(KlB[(kt + 1) & 1], kbl + (size_t)(kt + 1) * 64 * DK, DK);
            cpa_tile(VhB[(kt + 1) & 1], vbh + (kt + 1) * 64, SEQ);
            cpa_tile(VlB[(kt + 1) & 1], vbl + (kt + 1) * 64, SEQ);
            CP_COMMIT;
        }
        const int k0 = kt * 64, buf = kt & 1;
        float s[4][4];
        qk_mma(s, KhB[buf], KlB[buf]);

        float mi0 = mrow[wm * 16 + cr], mi1 = mrow[wm * 16 + cr + 8];
        float li0 = lrow[wm * 16 + cr], li1 = lrow[wm * 16 + cr + 8];
#pragma unroll
        for (int nt = 0; nt < 4; ++nt)
#pragma unroll
            for (int half = 0; half < 2; ++half) {
                int i = wm * 16 + cr + 8 * half;
                int j = wn * 32 + nt * 8 + 2 * cc;
                float mi = half ? mi1 : mi0;
                float li = half ? li1 : li0;
                float v0 = s[nt][2 * half] * scale;
                float v1 = s[nt][2 * half + 1] * scale;
                if (k0 + j > q0 + i) v0 = NEG_BIG;
                if (k0 + j + 1 > q0 + i) v1 = NEG_BIG;
                float p0 = __expf(v0 - mi) * li;
                float p1 = __expf(v1 - mi) * li;
                if (write_attn)
                    *(float2*)(attn_base + (size_t)i * SEQ + k0 + j) = make_float2(p0, p1);
                bf16 ph0, pl0, ph1, pl1;
                split2(p0, ph0, pl0); split2(p1, ph1, pl1);
                *(uint32_t*)&Ph[i * A_LDS + j] = pack2(ph0, ph1);
                *(uint32_t*)&Pl[i * A_LDS + j] = pack2(pl0, pl1);
            }
        __syncthreads();

#pragma unroll
        for (int kc = 0; kc < 4; ++kc) {
            uint32_t af[4], alf[4], bf[4][2], blf[4][2];
            {
                int row = wm * 16 + lr + 8 * (lm & 1);
                int col = kc * 16 + 8 * (lm >> 1);
                ldsm4(af[0], af[1], af[2], af[3], sptr(&Ph[row * A_LDS + col]));
                ldsm4(alf[0], alf[1], alf[2], alf[3], sptr(&Pl[row * A_LDS + col]));
            }
#pragma unroll
            for (int g = 0; g < 2; ++g) {
                int row = wn * 32 + g * 16 + 8 * (lm >> 1) + lr;
                int col = kc * 16 + 8 * (lm & 1);
                ldsm4(bf[2 * g][0], bf[2 * g][1], bf[2 * g + 1][0], bf[2 * g + 1][1],
                      sptr(&VhB[buf][row * A_LDS + col]));
                ldsm4(blf[2 * g][0], blf[2 * g][1], blf[2 * g + 1][0], blf[2 * g + 1][1],
                      sptr(&VlB[buf][row * A_LDS + col]));
            }
#pragma unroll
            for (int nt = 0; nt < 4; ++nt) {
                mma_bf16(o[nt], af, bf[nt][0], bf[nt][1]);
                mma_bf16(o[nt], af, blf[nt][0], blf[nt][1]);
                mma_bf16(o[nt], alf, bf[nt][0], bf[nt][1]);
            }
        }
    }

    // store O pre-split for the W_o GEMM
#pragma unroll
    for (int nt = 0; nt < 4; ++nt)
#pragma unroll
        for (int half = 0; half < 2; ++half) {
            int i = wm * 16 + cr + 8 * half;
            int d = wn * 32 + nt * 8 + 2 * cc;
            bf16 h0, l0, h1, l1;
            split2(o[nt][2 * half], h0, l0);
            split2(o[nt][2 * half + 1], h1, l1);
            size_t idx = (size_t)(b * SEQ + q0 + i) * DMODEL + h * DK + d;
            *(uint32_t*)(aoh + idx) = pack2(h0, h1);
            *(uint32_t*)(aol + idx) = pack2(l0, l1);
        }
}

// ---------------------------------------------------------------------------
// Launch
// ---------------------------------------------------------------------------
extern "C" void kernel_launch(void* const* d_in, const int* in_sizes, int n_in,
                              void* d_out, int out_size)
{
    const float* Q   = (const float*)d_in[0];
    const float* K   = (const float*)d_in[1];
    const float* V   = (const float*)d_in[2];
    const float* W_q = (const float*)d_in[3];
    const float* W_k = (const float*)d_in[4];
    const float* W_v = (const float*)d_in[5];
    const float* W_o = (const float*)d_in[6];
    const float* b_o = (const float*)d_in[7];
    float* out = (float*)d_out;

    const int write_attn = ((size_t)out_size > OUT_ELEMS) ? 1 : 0;
    float* attn = write_attn ? out + OUT_ELEMS : (float*)0;

    bf16 *xh, *xl, *wh, *wl, *qh, *ql, *kh, *kl, *vh, *vl, *aoh, *aol;
    cudaGetSymbolAddress((void**)&xh, g_xh);  cudaGetSymbolAddress((void**)&xl, g_xl);
    cudaGetSymbolAddress((void**)&wh, g_wh);  cudaGetSymbolAddress((void**)&wl, g_wl);
    cudaGetSymbolAddress((void**)&qh, g_qh);  cudaGetSymbolAddress((void**)&ql, g_ql);
    cudaGetSymbolAddress((void**)&kh, g_kh);  cudaGetSymbolAddress((void**)&kl, g_kl);
    cudaGetSymbolAddress((void**)&vh, g_vh);  cudaGetSymbolAddress((void**)&vl, g_vl);
    cudaGetSymbolAddress((void**)&aoh, g_aoh); cudaGetSymbolAddress((void**)&aol, g_aol);

    cudaFuncSetAttribute(gemm_bf16<0>, cudaFuncAttributeMaxDynamicSharedMemorySize, SMEM_GEMM_BYTES);
    cudaFuncSetAttribute(gemm_bf16<1>, cudaFuncAttributeMaxDynamicSharedMemorySize, SMEM_GEMM_BYTES);
    cudaFuncSetAttribute(gemm_bf16<2>, cudaFuncAttributeMaxDynamicSharedMemorySize, SMEM_GEMM_BYTES);
    cudaFuncSetAttribute(attn_split,   cudaFuncAttributeMaxDynamicSharedMemorySize, SMEM_ATTN_BYTES);

    const int n4x = MROWS * DMODEL / 4;     // 1,048,576
    const int n4w = DMODEL * DMODEL / 4;    // 262,144
    dim3 ggrid(DMODEL / 128, MROWS / 128);  // (8, 32)

    split_kernel<<<n4x / 256, 256>>>(Q,   xh, xl, n4x);
    split_kernel<<<n4w / 256, 256>>>(W_q, wh, wl, n4w);
    gemm_bf16<0><<<ggrid, 256, SMEM_GEMM_BYTES>>>(xh, xl, wh, wl, (float*)0, (const float*)0, qh, ql);

    split_kernel<<<n4x / 256, 256>>>(K,   xh, xl, n4x);
    split_kernel<<<n4w / 256, 256>>>(W_k, wh, wl, n4w);
    gemm_bf16<0><<<ggrid, 256, SMEM_GEMM_BYTES>>>(xh, xl, wh, wl, (float*)0, (const float*)0, kh, kl);

    split_kernel<<<n4x / 256, 256>>>(V,   xh, xl, n4x);
    split_kernel<<<n4w / 256, 256>>>(W_v, wh, wl, n4w);
    gemm_bf16<1><<<ggrid, 256, SMEM_GEMM_BYTES>>>(xh, xl, wh, wl, (float*)0, (const float*)0, vh, vl);

    dim3 agrid(SEQ / 64, NHEADS, BATCH);    // (32, 16, 2)
    attn_split<<<agrid, 256, SMEM_ATTN_BYTES>>>(qh, ql, kh, kl, vh, vl, attn, aoh, aol, write_attn);

    split_kernel<<<n4w / 256, 256>>>(W_o, wh, wl, n4w);
    gemm_bf16<2><<<ggrid, 256, SMEM_GEMM_BYTES>>>(aoh, aol, wh, wl, out, b_o,
                                                  (bf16*)0, (bf16*)0);
}

// round 4
// speedup vs baseline: 2.7520x; 1.0441x over previous
#include <cuda_runtime.h>
#include <cuda_bf16.h>
#include <stdint.h>

#define BATCH   2
#define SEQ     2048
#define DMODEL  1024
#define NHEADS  16
#define DK      64
#define MROWS   (BATCH * SEQ)                      // 4096
#define OUT_ELEMS ((size_t)MROWS * DMODEL)

typedef __nv_bfloat16 bf16;

// ---------------- scratch (device globals) ----------------
__device__ static bf16 g_qxh[MROWS * DMODEL], g_qxl[MROWS * DMODEL];
__device__ static bf16 g_kxh[MROWS * DMODEL], g_kxl[MROWS * DMODEL];
__device__ static bf16 g_vxh[MROWS * DMODEL], g_vxl[MROWS * DMODEL];
__device__ static bf16 g_wqh[DMODEL * DMODEL], g_wql[DMODEL * DMODEL];
__device__ static bf16 g_wkh[DMODEL * DMODEL], g_wkl[DMODEL * DMODEL];
__device__ static bf16 g_wvh[DMODEL * DMODEL], g_wvl[DMODEL * DMODEL];
__device__ static bf16 g_woh[DMODEL * DMODEL], g_wol[DMODEL * DMODEL];
__device__ static bf16 g_qh[MROWS * DMODEL],  g_ql[MROWS * DMODEL];
__device__ static bf16 g_kh[MROWS * DMODEL],  g_kl[MROWS * DMODEL];
__device__ static bf16 g_vh[MROWS * DMODEL],  g_vl[MROWS * DMODEL];   // [b][h][d][s]
__device__ static bf16 g_aoh[MROWS * DMODEL], g_aol[MROWS * DMODEL];

// ---------------- helpers ----------------
__device__ __forceinline__ uint32_t sptr(const void* p) {
    return (uint32_t)__cvta_generic_to_shared(p);
}
__device__ __forceinline__ void ldsm4(uint32_t& r0, uint32_t& r1, uint32_t& r2,
                                      uint32_t& r3, uint32_t a) {
    asm volatile("ldmatrix.sync.aligned.m8n8.x4.shared.b16 {%0,%1,%2,%3},[%4];"
                 : "=r"(r0), "=r"(r1), "=r"(r2), "=r"(r3) : "r"(a));
}
__device__ __forceinline__ void mma_bf16(float c[4], const uint32_t a[4],
                                         uint32_t b0, uint32_t b1) {
    asm volatile(
        "mma.sync.aligned.m16n8k16.row.col.f32.bf16.bf16.f32 "
        "{%0,%1,%2,%3},{%4,%5,%6,%7},{%8,%9},{%0,%1,%2,%3};"
        : "+f"(c[0]), "+f"(c[1]), "+f"(c[2]), "+f"(c[3])
        : "r"(a[0]), "r"(a[1]), "r"(a[2]), "r"(a[3]), "r"(b0), "r"(b1));
}
__device__ __forceinline__ void split2(float x, bf16& h, bf16& l) {
    h = __float2bfloat16(x);
    l = __float2bfloat16(x - __bfloat162float(h));
}
__device__ __forceinline__ uint32_t pack2(bf16 a, bf16 b) {
    __nv_bfloat162 t; t.x = a; t.y = b;
    return *(uint32_t*)&t;
}
__device__ __forceinline__ void cpa16(void* dst, const void* src) {
    asm volatile("cp.async.cg.shared.global [%0],[%1],16;"
                 :: "r"(sptr(dst)), "l"(__cvta_generic_to_global(src)));
}
#define CP_COMMIT  asm volatile("cp.async.commit_group;")
#define CP_WAIT0   asm volatile("cp.async.wait_group 0;")

// ---------------- split kernel: fp32 -> bf16 hi/lo ----------------
__global__ __launch_bounds__(256)
void split_kernel(const float* __restrict__ in, bf16* __restrict__ oh,
                  bf16* __restrict__ ol, int n4)
{
    int i = blockIdx.x * blockDim.x + threadIdx.x;
    if (i >= n4) return;
    float4 v = ((const float4*)in)[i];
    bf16 h0, l0, h1, l1, h2, l2, h3, l3;
    split2(v.x, h0, l0); split2(v.y, h1, l1);
    split2(v.z, h2, l2); split2(v.w, h3, l3);
    ((uint2*)oh)[i] = make_uint2(pack2(h0, h1), pack2(h2, h3));
    ((uint2*)ol)[i] = make_uint2(pack2(l0, l1), pack2(l2, l3));
}

// ---------------------------------------------------------------------------
// GEMM: C[4096,1024] = A @ B^T, pre-split bf16. 128x128x32, 8 warps (2x4).
// ---------------------------------------------------------------------------
#define G_LDS 40
#define G_TILE (128 * G_LDS)
#define SMEM_GEMM_BYTES (8 * G_TILE * 2)     // 81920

template <int EPI>
__global__ __launch_bounds__(256)
void gemm_bf16(const bf16* __restrict__ Ah, const bf16* __restrict__ Al,
               const bf16* __restrict__ Bh, const bf16* __restrict__ Bl,
               float* __restrict__ Cout, const float* __restrict__ bias,
               bf16* __restrict__ oh, bf16* __restrict__ ol)
{
    extern __shared__ bf16 smg[];
    const int t = threadIdx.x;
    const int m0 = blockIdx.y * 128, n0 = blockIdx.x * 128;
    const int w = t >> 5, lane = t & 31;
    const int wm = w >> 2, wn = w & 3;
    const int lm = lane >> 3, lr = lane & 7;

    float acc[4][4][4];
#pragma unroll
    for (int i = 0; i < 4; ++i)
#pragma unroll
        for (int j = 0; j < 4; ++j)
#pragma unroll
            for (int e = 0; e < 4; ++e) acc[i][j][e] = 0.f;

    auto issue = [&](int kk) {
        bf16* d = smg + (kk & 1) * 4 * G_TILE;
        const bf16* srcs[4] = {
            Ah + (size_t)m0 * DMODEL + kk * 32, Al + (size_t)m0 * DMODEL + kk * 32,
            Bh + (size_t)n0 * DMODEL + kk * 32, Bl + (size_t)n0 * DMODEL + kk * 32};
        const int r = t >> 2, o = (t & 3) * 8;
#pragma unroll
        for (int tl = 0; tl < 4; ++tl) {
            cpa16(d + tl * G_TILE + r * G_LDS + o,        srcs[tl] + (size_t)r * DMODEL + o);
            cpa16(d + tl * G_TILE + (r + 64) * G_LDS + o, srcs[tl] + (size_t)(r + 64) * DMODEL + o);
        }
    };

    issue(0); CP_COMMIT;

    const int NK = DMODEL / 32;
    for (int kk = 0; kk < NK; ++kk) {
        CP_WAIT0;
        __syncthreads();
        if (kk + 1 < NK) { issue(kk + 1); CP_COMMIT; }
        const bf16* sAh = smg + (kk & 1) * 4 * G_TILE;
        const bf16* sAl = sAh + G_TILE;
        const bf16* sBh = sAl + G_TILE;
        const bf16* sBl = sBh + G_TILE;
#pragma unroll
        for (int k16 = 0; k16 < 32; k16 += 16) {
            uint32_t ah[4][4], al[4][4], bh[4][2], bl[4][2];
#pragma unroll
            for (int mt = 0; mt < 4; ++mt) {
                int row = wm * 64 + mt * 16 + lr + 8 * (lm & 1);
                int col = k16 + 8 * (lm >> 1);
                ldsm4(ah[mt][0], ah[mt][1], ah[mt][2], ah[mt][3], sptr(&sAh[row * G_LDS + col]));
                ldsm4(al[mt][0], al[mt][1], al[mt][2], al[mt][3], sptr(&sAl[row * G_LDS + col]));
            }
#pragma unroll
            for (int g = 0; g < 2; ++g) {
                int row = wn * 32 + g * 16 + 8 * (lm >> 1) + lr;
                int col = k16 + 8 * (lm & 1);
                ldsm4(bh[2 * g][0], bh[2 * g][1], bh[2 * g + 1][0], bh[2 * g + 1][1],
                      sptr(&sBh[row * G_LDS + col]));
                ldsm4(bl[2 * g][0], bl[2 * g][1], bl[2 * g + 1][0], bl[2 * g + 1][1],
                      sptr(&sBl[row * G_LDS + col]));
            }
#pragma unroll
            for (int mt = 0; mt < 4; ++mt)
#pragma unroll
                for (int nt = 0; nt < 4; ++nt) {
                    mma_bf16(acc[mt][nt], ah[mt], bh[nt][0], bh[nt][1]);
                    mma_bf16(acc[mt][nt], ah[mt], bl[nt][0], bl[nt][1]);
                    mma_bf16(acc[mt][nt], al[mt], bh[nt][0], bh[nt][1]);
                }
        }
    }

    const int cr = lane >> 2, cc = lane & 3;
#pragma unroll
    for (int mt = 0; mt < 4; ++mt)
#pragma unroll
        for (int nt = 0; nt < 4; ++nt)
#pragma unroll
            for (int half = 0; half < 2; ++half) {
                int gm = m0 + wm * 64 + mt * 16 + cr + 8 * half;
                int gn = n0 + wn * 32 + nt * 8 + 2 * cc;
                float v0 = acc[mt][nt][2 * half + 0];
                float v1 = acc[mt][nt][2 * half + 1];
                if (EPI == 2) {
                    *(float2*)(Cout + (size_t)gm * DMODEL + gn) =
                        make_float2(v0 + bias[gn], v1 + bias[gn + 1]);
                } else {
                    int b = gm >> 11, s = gm & 2047, h = gn >> 6, d = gn & 63;
                    bf16 h0, l0, h1, l1;
                    split2(v0, h0, l0); split2(v1, h1, l1);
                    if (EPI == 0) {
                        size_t idx = (((size_t)(b * NHEADS + h) * SEQ) + s) * DK + d;
                        *(uint32_t*)(oh + idx) = pack2(h0, h1);
                        *(uint32_t*)(ol + idx) = pack2(l0, l1);
                    } else {
                        size_t idx = (((size_t)(b * NHEADS + h) * DK) + d) * SEQ + s;
                        oh[idx] = h0; ol[idx] = l0;
                        oh[idx + SEQ] = h1; ol[idx + SEQ] = l1;
                    }
                }
            }
}

// ---------------------------------------------------------------------------
// Attention: FA2 register-reuse, max-free two-pass, per (q-tile 64, h, b).
// 8 warps: wm = w>>1 (rows), wn = w&1 (j-slice 32 wide).
// ---------------------------------------------------------------------------
#define A_LDS 72
#define A_TILE (64 * A_LDS)
#define SMEM_ATTN_BYTES (10 * A_TILE * 2 + 128 * 4 + 64 * 4)   // 92928

__global__ __launch_bounds__(256, 2)
void attn_fa2(const bf16* __restrict__ qh, const bf16* __restrict__ ql,
              const bf16* __restrict__ kh, const bf16* __restrict__ kl,
              const bf16* __restrict__ vh, const bf16* __restrict__ vl,
              float* __restrict__ attn, bf16* __restrict__ aoh,
              bf16* __restrict__ aol, int write_attn)
{
    extern __shared__ bf16 sma[];
    bf16* Qh = sma;
    bf16* Ql = sma + A_TILE;
    bf16* KhB[2] = {sma + 2 * A_TILE, sma + 3 * A_TILE};
    bf16* KlB[2] = {sma + 4 * A_TILE, sma + 5 * A_TILE};
    bf16* VhB[2] = {sma + 6 * A_TILE, sma + 7 * A_TILE};
    bf16* VlB[2] = {sma + 8 * A_TILE, sma + 9 * A_TILE};
    float* lsum = (float*)(sma + 10 * A_TILE);   // [2][64]
    float* lrow = lsum + 128;                    // [64] 1/l
    float* red  = (float*)(sma + 2 * A_TILE);    // 16KB, aliases K bufs (end only)

    const int qt = blockIdx.x, h = blockIdx.y, b = blockIdx.z;
    const int q0 = qt * 64;
    const int t = threadIdx.x, w = t >> 5, lane = t & 31;
    const int wm = w >> 1, wn = w & 1;
    const int lm = lane >> 3, lr = lane & 7;
    const int cr = lane >> 2, cc = lane & 3;
    const float scale = 0.125f;

    const size_t bh = (size_t)(b * NHEADS + h);
    const bf16* qbh = qh + bh * SEQ * DK;
    const bf16* qbl = ql + bh * SEQ * DK;
    const bf16* kbh = kh + bh * SEQ * DK;
    const bf16* kbl = kl + bh * SEQ * DK;
    const bf16* vbh = vh + bh * DK * SEQ;
    const bf16* vbl = vl + bh * DK * SEQ;

    auto cpa_tile = [&](bf16* dst, const bf16* src, int rstride) {
        const int r = t >> 3, o = (t & 7) * 8;
        cpa16(dst + r * A_LDS + o,        src + (size_t)r * rstride + o);
        cpa16(dst + (r + 32) * A_LDS + o, src + (size_t)(r + 32) * rstride + o);
    };

    // QK^T mma: s[nt][e] for one 64x64 tile (warp: rows wm*16.., j wn*32..)
    auto qk_mma = [&](float s[4][4], const bf16* KH, const bf16* KL) {
#pragma unroll
        for (int nt = 0; nt < 4; ++nt)
#pragma unroll
            for (int e = 0; e < 4; ++e) s[nt][e] = 0.f;
#pragma unroll
        for (int kc = 0; kc < 4; ++kc) {
            uint32_t af[4], alf[4], bf[4][2], blf[4][2];
            {
                int row = wm * 16 + lr + 8 * (lm & 1);
                int col = kc * 16 + 8 * (lm >> 1);
                ldsm4(af[0], af[1], af[2], af[3], sptr(&Qh[row * A_LDS + col]));
                ldsm4(alf[0], alf[1], alf[2], alf[3], sptr(&Ql[row * A_LDS + col]));
            }
#pragma unroll
            for (int g = 0; g < 2; ++g) {
                int row = wn * 32 + g * 16 + 8 * (lm >> 1) + lr;
                int col = kc * 16 + 8 * (lm & 1);
                ldsm4(bf[2 * g][0], bf[2 * g][1], bf[2 * g + 1][0], bf[2 * g + 1][1],
                      sptr(&KH[row * A_LDS + col]));
                ldsm4(blf[2 * g][0], blf[2 * g][1], blf[2 * g + 1][0], blf[2 * g + 1][1],
                      sptr(&KL[row * A_LDS + col]));
            }
#pragma unroll
            for (int nt = 0; nt < 4; ++nt) {
                mma_bf16(s[nt], af, bf[nt][0], bf[nt][1]);
                mma_bf16(s[nt], af, blf[nt][0], blf[nt][1]);
                mma_bf16(s[nt], alf, bf[nt][0], bf[nt][1]);
            }
        }
    };

    // prologue: Q + K(0)
    cpa_tile(Qh, qbh + (size_t)q0 * DK, DK);
    cpa_tile(Ql, qbl + (size_t)q0 * DK, DK);
    cpa_tile(KhB[0], kbh, DK);
    cpa_tile(KlB[0], kbl, DK);
    CP_COMMIT;

    // ---------------- Pass 1: row sums (m == 0, no max tracking) ----------
    float lp0 = 0.f, lp1 = 0.f;
    for (int kt = 0; kt <= qt; ++kt) {
        CP_WAIT0;
        __syncthreads();
        if (kt + 1 <= qt) {
            cpa_tile(KhB[(kt + 1) & 1], kbh + (size_t)(kt + 1) * 64 * DK, DK);
            cpa_tile(KlB[(kt + 1) & 1], kbl + (size_t)(kt + 1) * 64 * DK, DK);
            CP_COMMIT;
        }
        const int k0 = kt * 64;
        float s[4][4];
        qk_mma(s, KhB[kt & 1], KlB[kt & 1]);
#pragma unroll
        for (int nt = 0; nt < 4; ++nt)
#pragma unroll
            for (int e = 0; e < 4; ++e) {
                int rg = q0 + wm * 16 + cr + 8 * (e >> 1);
                int jg = k0 + wn * 32 + nt * 8 + 2 * cc + (e & 1);
                if (jg <= rg) {
                    float ev = __expf(s[nt][e] * scale);
                    if (e >> 1) lp1 += ev; else lp0 += ev;
                }
            }
    }
    lp0 += __shfl_xor_sync(0xffffffff, lp0, 1);
    lp0 += __shfl_xor_sync(0xffffffff, lp0, 2);
    lp1 += __shfl_xor_sync(0xffffffff, lp1, 1);
    lp1 += __shfl_xor_sync(0xffffffff, lp1, 2);
    if (cc == 0) {
        lsum[wn * 64 + wm * 16 + cr]     = lp0;
        lsum[wn * 64 + wm * 16 + cr + 8] = lp1;
    }
    __syncthreads();
    if (t < 64) lrow[t] = 1.0f / (lsum[t] + lsum[64 + t]);

    // prologue for pass 2: K(0), V(0)
    cpa_tile(KhB[0], kbh, DK);
    cpa_tile(KlB[0], kbl, DK);
    cpa_tile(VhB[0], vbh, SEQ);
    cpa_tile(VlB[0], vbl, SEQ);
    CP_COMMIT;

    float* attn_base = write_attn ? attn + (bh * SEQ + q0) * SEQ : (float*)0;
    if (write_attn) {   // zero fully-masked tiles, overlapped with cp.async
        const int zr = t >> 2, zc = (t & 3) * 16;
        for (int kt = qt + 1; kt < SEQ / 64; ++kt) {
            float4 z = make_float4(0.f, 0.f, 0.f, 0.f);
            float* dst = attn_base + (size_t)zr * SEQ + kt * 64 + zc;
            *(float4*)(dst) = z; *(float4*)(dst + 4) = z;
            *(float4*)(dst + 8) = z; *(float4*)(dst + 12) = z;
        }
    }

    // ---------------- Pass 2: attn write + P@V (register-resident P) ------
    float o[8][4];      // 8 d-tiles of 8 x accumulator quad; j-partial (this wn)
#pragma unroll
    for (int nt = 0; nt < 8; ++nt)
#pragma unroll
        for (int e = 0; e < 4; ++e) o[nt][e] = 0.f;

    __syncthreads();    // lrow visible
    const float li0 = lrow[wm * 16 + cr];
    const float li1 = lrow[wm * 16 + cr + 8];

    for (int kt = 0; kt <= qt; ++kt) {
        CP_WAIT0;
        __syncthreads();
        if (kt + 1 <= qt) {
            cpa_tile(KhB[(kt + 1) & 1], kbh + (size_t)(kt + 1) * 64 * DK, DK);
            cpa_tile(KlB[(kt + 1) & 1], kbl + (size_t)(kt + 1) * 64 * DK, DK);
            cpa_tile(VhB[(kt + 1) & 1], vbh + (kt + 1) * 64, SEQ);
            cpa_tile(VlB[(kt + 1) & 1], vbl + (kt + 1) * 64, SEQ);
            CP_COMMIT;
        }
        const int k0 = kt * 64, buf = kt & 1;
        float s[4][4];
        qk_mma(s, KhB[buf], KlB[buf]);

        // p = exp(s*scale)/l, write attn, pack bf16 hi/lo A-fragments
        uint32_t php[4][2], plp[4][2];
#pragma unroll
        for (int nt = 0; nt < 4; ++nt) {
#pragma unroll
            for (int half = 0; half < 2; ++half) {
                int i = wm * 16 + cr + 8 * half;
                int j = wn * 32 + nt * 8 + 2 * cc;
                float li = half ? li1 : li0;
                float p0 = 0.f, p1 = 0.f;
                if (k0 + j     <= q0 + i) p0 = __expf(s[nt][2 * half]     * scale) * li;
                if (k0 + j + 1 <= q0 + i) p1 = __expf(s[nt][2 * half + 1] * scale) * li;
                if (write_attn)
                    *(float2*)(attn_base + (size_t)i * SEQ + k0 + j) = make_float2(p0, p1);
                bf16 h0, l0, h1, l1;
                split2(p0, h0, l0); split2(p1, h1, l1);
                php[nt][half] = pack2(h0, h1);
                plp[nt][half] = pack2(l0, l1);
            }
        }

        // O += P @ V over this warp's 32-wide j slice, all 64 d
#pragma unroll
        for (int kc = 0; kc < 2; ++kc) {
            uint32_t ah[4] = {php[2 * kc][0], php[2 * kc][1],
                              php[2 * kc + 1][0], php[2 * kc + 1][1]};
            uint32_t al[4] = {plp[2 * kc][0], plp[2 * kc][1],
                              plp[2 * kc + 1][0], plp[2 * kc + 1][1]};
#pragma unroll
            for (int g = 0; g < 4; ++g) {
                int row = g * 16 + 8 * (lm >> 1) + lr;                 // d
                int col = wn * 32 + kc * 16 + 8 * (lm & 1);            // j
                uint32_t bh0, bh1, bh2, bh3, bl0, bl1, bl2, bl3;
                ldsm4(bh0, bh1, bh2, bh3, sptr(&VhB[buf][row * A_LDS + col]));
                ldsm4(bl0, bl1, bl2, bl3, sptr(&VlB[buf][row * A_LDS + col]));
                mma_bf16(o[2 * g],     ah, bh0, bh1);
                mma_bf16(o[2 * g],     ah, bl0, bl1);
                mma_bf16(o[2 * g],     al, bh0, bh1);
                mma_bf16(o[2 * g + 1], ah, bh2, bh3);
                mma_bf16(o[2 * g + 1], ah, bl2, bl3);
                mma_bf16(o[2 * g + 1], al, bh2, bh3);
            }
        }
    }

    // ---------------- cross-warp (wn) O reduction + store -----------------
    __syncthreads();          // K/V buffers dead; reuse as reduction buffer
    if (wn == 1) {
#pragma unroll
        for (int nt = 0; nt < 8; ++nt)
#pragma unroll
            for (int half = 0; half < 2; ++half) {
                int i = wm * 16 + cr + 8 * half;
                int d = nt * 8 + 2 * cc;
                *(float2*)&red[i * 64 + d] =
                    make_float2(o[nt][2 * half], o[nt][2 * half + 1]);
            }
    }
    __syncthreads();
    if (wn == 0) {
#pragma unroll
        for (int nt = 0; nt < 8; ++nt)
#pragma unroll
            for (int half = 0; half < 2; ++half) {
                int i = wm * 16 + cr + 8 * half;
                int d = nt * 8 + 2 * cc;
                float2 r = *(float2*)&red[i * 64 + d];
                float v0 = o[nt][2 * half]     + r.x;
                float v1 = o[nt][2 * half + 1] + r.y;
                bf16 h0, l0, h1, l1;
                split2(v0, h0, l0); split2(v1, h1, l1);
                size_t idx = (size_t)(b * SEQ + q0 + i) * DMODEL + h * DK + d;
                *(uint32_t*)(aoh + idx) = pack2(h0, h1);
                *(uint32_t*)(aol + idx) = pack2(l0, l1);
            }
    }
}

// ---------------------------------------------------------------------------
// Launch
// ---------------------------------------------------------------------------
extern "C" void kernel_launch(void* const* d_in, const int* in_sizes, int n_in,
                              void* d_out, int out_size)
{
    const float* Q   = (const float*)d_in[0];
    const float* K   = (const float*)d_in[1];
    const float* V   = (const float*)d_in[2];
    const float* W_q = (const float*)d_in[3];
    const float* W_k = (const float*)d_in[4];
    const float* W_v = (const float*)d_in[5];
    const float* W_o = (const float*)d_in[6];
    const float* b_o = (const float*)d_in[7];
    float* out = (float*)d_out;

    const int write_attn = ((size_t)out_size > OUT_ELEMS) ? 1 : 0;
    float* attn = write_attn ? out + OUT_ELEMS : (float*)0;

    bf16 *qxh, *qxl, *kxh, *kxl, *vxh, *vxl;
    bf16 *wqh, *wql, *wkh, *wkl, *wvh, *wvl, *woh, *wol;
    bf16 *qh, *ql, *kh, *kl, *vh, *vl, *aoh, *aol;
    cudaGetSymbolAddress((void**)&qxh, g_qxh); cudaGetSymbolAddress((void**)&qxl, g_qxl);
    cudaGetSymbolAddress((void**)&kxh, g_kxh); cudaGetSymbolAddress((void**)&kxl, g_kxl);
    cudaGetSymbolAddress((void**)&vxh, g_vxh); cudaGetSymbolAddress((void**)&vxl, g_vxl);
    cudaGetSymbolAddress((void**)&wqh, g_wqh); cudaGetSymbolAddress((void**)&wql, g_wql);
    cudaGetSymbolAddress((void**)&wkh, g_wkh); cudaGetSymbolAddress((void**)&wkl, g_wkl);
    cudaGetSymbolAddress((void**)&wvh, g_wvh); cudaGetSymbolAddress((void**)&wvl, g_wvl);
    cudaGetSymbolAddress((void**)&woh, g_woh); cudaGetSymbolAddress((void**)&wol, g_wol);
    cudaGetSymbolAddress((void**)&qh, g_qh);   cudaGetSymbolAddress((void**)&ql, g_ql);
    cudaGetSymbolAddress((void**)&kh, g_kh);   cudaGetSymbolAddress((void**)&kl, g_kl);
    cudaGetSymbolAddress((void**)&vh, g_vh);   cudaGetSymbolAddress((void**)&vl, g_vl);
    cudaGetSymbolAddress((void**)&aoh, g_aoh); cudaGetSymbolAddress((void**)&aol, g_aol);

    cudaFuncSetAttribute(gemm_bf16<0>, cudaFuncAttributeMaxDynamicSharedMemorySize, SMEM_GEMM_BYTES);
    cudaFuncSetAttribute(gemm_bf16<1>, cudaFuncAttributeMaxDynamicSharedMemorySize, SMEM_GEMM_BYTES);
    cudaFuncSetAttribute(gemm_bf16<2>, cudaFuncAttributeMaxDynamicSharedMemorySize, SMEM_GEMM_BYTES);
    cudaFuncSetAttribute(attn_fa2,     cudaFuncAttributeMaxDynamicSharedMemorySize, SMEM_ATTN_BYTES);

    const int n4x = MROWS * DMODEL / 4;
    const int n4w = DMODEL * DMODEL / 4;
    dim3 ggrid(DMODEL / 128, MROWS / 128);

    split_kernel<<<n4x / 256, 256>>>(Q,   qxh, qxl, n4x);
    split_kernel<<<n4x / 256, 256>>>(K,   kxh, kxl, n4x);
    split_kernel<<<n4x / 256, 256>>>(V,   vxh, vxl, n4x);
    split_kernel<<<n4w / 256, 256>>>(W_q, wqh, wql, n4w);
    split_kernel<<<n4w / 256, 256>>>(W_k, wkh, wkl, n4w);
    split_kernel<<<n4w / 256, 256>>>(W_v, wvh, wvl, n4w);
    split_kernel<<<n4w / 256, 256>>>(W_o, woh, wol, n4w);

    gemm_bf16<0><<<ggrid, 256, SMEM_GEMM_BYTES>>>(qxh, qxl, wqh, wql, (float*)0, (const float*)0, qh, ql);
    gemm_bf16<0><<<ggrid, 256, SMEM_GEMM_BYTES>>>(kxh, kxl, wkh, wkl, (float*)0, (const float*)0, kh, kl);
    gemm_bf16<1><<<ggrid, 256, SMEM_GEMM_BYTES>>>(vxh, vxl, wvh, wvl, (float*)0, (const float*)0, vh, vl);

    dim3 agrid(SEQ / 64, NHEADS, BATCH);
    attn_fa2<<<agrid, 256, SMEM_ATTN_BYTES>>>(qh, ql, kh, kl, vh, vl, attn, aoh, aol, write_attn);

    gemm_bf16<2><<<ggrid, 256, SMEM_GEMM_BYTES>>>(aoh, aol, woh, wol, out, b_o,
                                                  (bf16*)0, (bf16*)0);
}

// round 6
// speedup vs baseline: 2.7660x; 1.0051x over previous
#include <cuda_runtime.h>
#include <cuda_bf16.h>
#include <stdint.h>

#define BATCH   2
#define SEQ     2048
#define DMODEL  1024
#define NHEADS  16
#define DK      64
#define MROWS   (BATCH * SEQ)                      // 4096
#define OUT_ELEMS ((size_t)MROWS * DMODEL)

typedef __nv_bfloat16 bf16;

// ---------------- scratch (device globals) ----------------
__device__ static bf16 g_qxh[MROWS * DMODEL], g_qxl[MROWS * DMODEL];
__device__ static bf16 g_kxh[MROWS * DMODEL], g_kxl[MROWS * DMODEL];
__device__ static bf16 g_vxh[MROWS * DMODEL], g_vxl[MROWS * DMODEL];
__device__ static bf16 g_wqh[DMODEL * DMODEL], g_wql[DMODEL * DMODEL];
__device__ static bf16 g_wkh[DMODEL * DMODEL], g_wkl[DMODEL * DMODEL];
__device__ static bf16 g_wvh[DMODEL * DMODEL], g_wvl[DMODEL * DMODEL];
__device__ static bf16 g_woh[DMODEL * DMODEL], g_wol[DMODEL * DMODEL];
__device__ static bf16 g_qh[MROWS * DMODEL],  g_ql[MROWS * DMODEL];
__device__ static bf16 g_kh[MROWS * DMODEL],  g_kl[MROWS * DMODEL];
__device__ static bf16 g_vh[MROWS * DMODEL],  g_vl[MROWS * DMODEL];   // [b][h][d][s]
__device__ static bf16 g_aoh[MROWS * DMODEL], g_aol[MROWS * DMODEL];
__device__ static float g_linv[BATCH * NHEADS * SEQ];

// ---------------- helpers ----------------
__device__ __forceinline__ uint32_t sptr(const void* p) {
    return (uint32_t)__cvta_generic_to_shared(p);
}
__device__ __forceinline__ void ldsm4(uint32_t& r0, uint32_t& r1, uint32_t& r2,
                                      uint32_t& r3, uint32_t a) {
    asm volatile("ldmatrix.sync.aligned.m8n8.x4.shared.b16 {%0,%1,%2,%3},[%4];"
                 : "=r"(r0), "=r"(r1), "=r"(r2), "=r"(r3) : "r"(a));
}
__device__ __forceinline__ void mma_bf16(float c[4], const uint32_t a[4],
                                         uint32_t b0, uint32_t b1) {
    asm volatile(
        "mma.sync.aligned.m16n8k16.row.col.f32.bf16.bf16.f32 "
        "{%0,%1,%2,%3},{%4,%5,%6,%7},{%8,%9},{%0,%1,%2,%3};"
        : "+f"(c[0]), "+f"(c[1]), "+f"(c[2]), "+f"(c[3])
        : "r"(a[0]), "r"(a[1]), "r"(a[2]), "r"(a[3]), "r"(b0), "r"(b1));
}
__device__ __forceinline__ void split2(float x, bf16& h, bf16& l) {
    h = __float2bfloat16(x);
    l = __float2bfloat16(x - __bfloat162float(h));
}
__device__ __forceinline__ uint32_t pack2(bf16 a, bf16 b) {
    __nv_bfloat162 t; t.x = a; t.y = b;
    return *(uint32_t*)&t;
}
__device__ __forceinline__ void cpa16(void* dst, const void* src) {
    asm volatile("cp.async.cg.shared.global [%0],[%1],16;"
                 :: "r"(sptr(dst)), "l"(__cvta_generic_to_global(src)));
}
#define CP_COMMIT  asm volatile("cp.async.commit_group;")
#define CP_WAIT0   asm volatile("cp.async.wait_group 0;")

// ---------------- split kernel: fp32 -> bf16 hi/lo ----------------
__global__ __launch_bounds__(256)
void split_kernel(const float* __restrict__ in, bf16* __restrict__ oh,
                  bf16* __restrict__ ol, int n4)
{
    int i = blockIdx.x * blockDim.x + threadIdx.x;
    if (i >= n4) return;
    float4 v = ((const float4*)in)[i];
    bf16 h0, l0, h1, l1, h2, l2, h3, l3;
    split2(v.x, h0, l0); split2(v.y, h1, l1);
    split2(v.z, h2, l2); split2(v.w, h3, l3);
    ((uint2*)oh)[i] = make_uint2(pack2(h0, h1), pack2(h2, h3));
    ((uint2*)ol)[i] = make_uint2(pack2(l0, l1), pack2(l2, l3));
}

// ---------------------------------------------------------------------------
// GEMM: C[4096,1024] = A @ B^T, pre-split bf16. 128x128x32, 8 warps (2x4).
// EPI 0: bf16 hi/lo out [b][h][s][d]; 1: transposed [b][h][d][s]; 2: fp32+bias
// ---------------------------------------------------------------------------
#define G_LDS 40
#define G_TILE (128 * G_LDS)
#define SMEM_GEMM_BYTES (8 * G_TILE * 2)     // 81920

template <int EPI>
__global__ __launch_bounds__(256)
void gemm_bf16(const bf16* __restrict__ Ah, const bf16* __restrict__ Al,
               const bf16* __restrict__ Bh, const bf16* __restrict__ Bl,
               float* __restrict__ Cout, const float* __restrict__ bias,
               bf16* __restrict__ oh, bf16* __restrict__ ol)
{
    extern __shared__ bf16 smg[];
    const int t = threadIdx.x;
    const int m0 = blockIdx.y * 128, n0 = blockIdx.x * 128;
    const int w = t >> 5, lane = t & 31;
    const int wm = w >> 2, wn = w & 3;
    const int lm = lane >> 3, lr = lane & 7;

    float acc[4][4][4];
#pragma unroll
    for (int i = 0; i < 4; ++i)
#pragma unroll
        for (int j = 0; j < 4; ++j)
#pragma unroll
            for (int e = 0; e < 4; ++e) acc[i][j][e] = 0.f;

    auto issue = [&](int kk) {
        bf16* d = smg + (kk & 1) * 4 * G_TILE;
        const bf16* srcs[4] = {
            Ah + (size_t)m0 * DMODEL + kk * 32, Al + (size_t)m0 * DMODEL + kk * 32,
            Bh + (size_t)n0 * DMODEL + kk * 32, Bl + (size_t)n0 * DMODEL + kk * 32};
        const int r = t >> 2, o = (t & 3) * 8;
#pragma unroll
        for (int tl = 0; tl < 4; ++tl) {
            cpa16(d + tl * G_TILE + r * G_LDS + o,        srcs[tl] + (size_t)r * DMODEL + o);
            cpa16(d + tl * G_TILE + (r + 64) * G_LDS + o, srcs[tl] + (size_t)(r + 64) * DMODEL + o);
        }
    };

    issue(0); CP_COMMIT;

    const int NK = DMODEL / 32;
    for (int kk = 0; kk < NK; ++kk) {
        CP_WAIT0;
        __syncthreads();
        if (kk + 1 < NK) { issue(kk + 1); CP_COMMIT; }
        const bf16* sAh = smg + (kk & 1) * 4 * G_TILE;
        const bf16* sAl = sAh + G_TILE;
        const bf16* sBh = sAl + G_TILE;
        const bf16* sBl = sBh + G_TILE;
#pragma unroll
        for (int k16 = 0; k16 < 32; k16 += 16) {
            uint32_t ah[4][4], al[4][4], bh[4][2], bl[4][2];
#pragma unroll
            for (int mt = 0; mt < 4; ++mt) {
                int row = wm * 64 + mt * 16 + lr + 8 * (lm & 1);
                int col = k16 + 8 * (lm >> 1);
                ldsm4(ah[mt][0], ah[mt][1], ah[mt][2], ah[mt][3], sptr(&sAh[row * G_LDS + col]));
                ldsm4(al[mt][0], al[mt][1], al[mt][2], al[mt][3], sptr(&sAl[row * G_LDS + col]));
            }
#pragma unroll
            for (int g = 0; g < 2; ++g) {
                int row = wn * 32 + g * 16 + 8 * (lm >> 1) + lr;
                int col = k16 + 8 * (lm & 1);
                ldsm4(bh[2 * g][0], bh[2 * g][1], bh[2 * g + 1][0], bh[2 * g + 1][1],
                      sptr(&sBh[row * G_LDS + col]));
                ldsm4(bl[2 * g][0], bl[2 * g][1], bl[2 * g + 1][0], bl[2 * g + 1][1],
                      sptr(&sBl[row * G_LDS + col]));
            }
#pragma unroll
            for (int mt = 0; mt < 4; ++mt)
#pragma unroll
                for (int nt = 0; nt < 4; ++nt) {
                    mma_bf16(acc[mt][nt], ah[mt], bh[nt][0], bh[nt][1]);
                    mma_bf16(acc[mt][nt], ah[mt], bl[nt][0], bl[nt][1]);
                    mma_bf16(acc[mt][nt], al[mt], bh[nt][0], bh[nt][1]);
                }
        }
    }

    const int cr = lane >> 2, cc = lane & 3;
#pragma unroll
    for (int mt = 0; mt < 4; ++mt)
#pragma unroll
        for (int nt = 0; nt < 4; ++nt)
#pragma unroll
            for (int half = 0; half < 2; ++half) {
                int gm = m0 + wm * 64 + mt * 16 + cr + 8 * half;
                int gn = n0 + wn * 32 + nt * 8 + 2 * cc;
                float v0 = acc[mt][nt][2 * half + 0];
                float v1 = acc[mt][nt][2 * half + 1];
                if (EPI == 2) {
                    *(float2*)(Cout + (size_t)gm * DMODEL + gn) =
                        make_float2(v0 + bias[gn], v1 + bias[gn + 1]);
                } else {
                    int b = gm >> 11, s = gm & 2047, h = gn >> 6, d = gn & 63;
                    bf16 h0, l0, h1, l1;
                    split2(v0, h0, l0); split2(v1, h1, l1);
                    if (EPI == 0) {
                        size_t idx = (((size_t)(b * NHEADS + h) * SEQ) + s) * DK + d;
                        *(uint32_t*)(oh + idx) = pack2(h0, h1);
                        *(uint32_t*)(ol + idx) = pack2(l0, l1);
                    } else {
                        size_t idx = (((size_t)(b * NHEADS + h) * DK) + d) * SEQ + s;
                        oh[idx] = h0; ol[idx] = l0;
                        oh[idx + SEQ] = h1; ol[idx + SEQ] = l1;
                    }
                }
            }
}

// ---------------------------------------------------------------------------
// Single-pass attention (m == 0): unnormalized p -> attn, O and l in regs,
// O scaled in-kernel; attn normalized by attn_norm afterwards.
// 8 warps: wm = w>>1 (16-row slice), wn = w&1 (32-wide j slice).
// Heavy tiles first: qt = 31 - blockIdx.x.
// ---------------------------------------------------------------------------
#define A_LDS 72
#define A_TILE (64 * A_LDS)
#define SMEM_ATTN_BYTES (10 * A_TILE * 2 + 128 * 4 + 64 * 4)   // 92928

__global__ __launch_bounds__(256, 2)
void attn_1p(const bf16* __restrict__ qh, const bf16* __restrict__ ql,
             const bf16* __restrict__ kh, const bf16* __restrict__ kl,
             const bf16* __restrict__ vh, const bf16* __restrict__ vl,
             float* __restrict__ attn, bf16* __restrict__ aoh,
             bf16* __restrict__ aol, float* __restrict__ linv_g,
             int write_attn)
{
    extern __shared__ bf16 sma[];
    bf16* Qh = sma;
    bf16* Ql = sma + A_TILE;
    bf16* KhB[2] = {sma + 2 * A_TILE, sma + 3 * A_TILE};
    bf16* KlB[2] = {sma + 4 * A_TILE, sma + 5 * A_TILE};
    bf16* VhB[2] = {sma + 6 * A_TILE, sma + 7 * A_TILE};
    bf16* VlB[2] = {sma + 8 * A_TILE, sma + 9 * A_TILE};
    float* lsum = (float*)(sma + 10 * A_TILE);   // [2][64]
    float* lrow = lsum + 128;                    // [64]
    float* red  = (float*)(sma + 2 * A_TILE);    // aliases K bufs (end only)

    const int qt = (int)gridDim.x - 1 - (int)blockIdx.x;   // heavy first
    const int h = blockIdx.y, b = blockIdx.z;
    const int q0 = qt * 64;
    const int t = threadIdx.x, w = t >> 5, lane = t & 31;
    const int wm = w >> 1, wn = w & 1;
    const int lm = lane >> 3, lr = lane & 7;
    const int cr = lane >> 2, cc = lane & 3;
    const float scale = 0.125f;

    const size_t bh = (size_t)(b * NHEADS + h);
    const bf16* qbh = qh + bh * SEQ * DK;
    const bf16* qbl = ql + bh * SEQ * DK;
    const bf16* kbh = kh + bh * SEQ * DK;
    const bf16* kbl = kl + bh * SEQ * DK;
    const bf16* vbh = vh + bh * DK * SEQ;
    const bf16* vbl = vl + bh * DK * SEQ;

    auto cpa_tile = [&](bf16* dst, const bf16* src, int rstride) {
        const int r = t >> 3, o = (t & 7) * 8;
        cpa16(dst + r * A_LDS + o,        src + (size_t)r * rstride + o);
        cpa16(dst + (r + 32) * A_LDS + o, src + (size_t)(r + 32) * rstride + o);
    };

    auto qk_mma = [&](float s[4][4], const bf16* KH, const bf16* KL) {
#pragma unroll
        for (int nt = 0; nt < 4; ++nt)
#pragma unroll
            for (int e = 0; e < 4; ++e) s[nt][e] = 0.f;
#pragma unroll
        for (int kc = 0; kc < 4; ++kc) {
            uint32_t af[4], alf[4], bfh[4][2], blf[4][2];
            {
                int row = wm * 16 + lr + 8 * (lm & 1);
                int col = kc * 16 + 8 * (lm >> 1);
                ldsm4(af[0], af[1], af[2], af[3], sptr(&Qh[row * A_LDS + col]));
                ldsm4(alf[0], alf[1], alf[2], alf[3], sptr(&Ql[row * A_LDS + col]));
            }
#pragma unroll
            for (int g = 0; g < 2; ++g) {
                int row = wn * 32 + g * 16 + 8 * (lm >> 1) + lr;
                int col = kc * 16 + 8 * (lm & 1);
                ldsm4(bfh[2 * g][0], bfh[2 * g][1], bfh[2 * g + 1][0], bfh[2 * g + 1][1],
                      sptr(&KH[row * A_LDS + col]));
                ldsm4(blf[2 * g][0], blf[2 * g][1], blf[2 * g + 1][0], blf[2 * g + 1][1],
                      sptr(&KL[row * A_LDS + col]));
            }
#pragma unroll
            for (int nt = 0; nt < 4; ++nt) {
                mma_bf16(s[nt], af, bfh[nt][0], bfh[nt][1]);
                mma_bf16(s[nt], af, blf[nt][0], blf[nt][1]);
                mma_bf16(s[nt], alf, bfh[nt][0], bfh[nt][1]);
            }
        }
    };

    // prologue: Q, K(0), V(0)
    cpa_tile(Qh, qbh + (size_t)q0 * DK, DK);
    cpa_tile(Ql, qbl + (size_t)q0 * DK, DK);
    cpa_tile(KhB[0], kbh, DK);
    cpa_tile(KlB[0], kbl, DK);
    cpa_tile(VhB[0], vbh, SEQ);
    cpa_tile(VlB[0], vbl, SEQ);
    CP_COMMIT;

    float* attn_base = write_attn ? attn + (bh * SEQ + q0) * SEQ : (float*)0;
    if (write_attn) {   // zero fully-masked tiles (overlaps cp.async)
        const int zr = t >> 2, zc = (t & 3) * 16;
        for (int kt = qt + 1; kt < SEQ / 64; ++kt) {
            float4 z = make_float4(0.f, 0.f, 0.f, 0.f);
            float* dst = attn_base + (size_t)zr * SEQ + kt * 64 + zc;
            *(float4*)(dst) = z; *(float4*)(dst + 4) = z;
            *(float4*)(dst + 8) = z; *(float4*)(dst + 12) = z;
        }
    }

    float o[8][4];      // unnormalized O partial over this warp's j slice
#pragma unroll
    for (int nt = 0; nt < 8; ++nt)
#pragma unroll
        for (int e = 0; e < 4; ++e) o[nt][e] = 0.f;
    float lp0 = 0.f, lp1 = 0.f;

    for (int kt = 0; kt <= qt; ++kt) {
        CP_WAIT0;
        __syncthreads();
        if (kt + 1 <= qt) {
            cpa_tile(KhB[(kt + 1) & 1], kbh + (size_t)(kt + 1) * 64 * DK, DK);
            cpa_tile(KlB[(kt + 1) & 1], kbl + (size_t)(kt + 1) * 64 * DK, DK);
            cpa_tile(VhB[(kt + 1) & 1], vbh + (kt + 1) * 64, SEQ);
            cpa_tile(VlB[(kt + 1) & 1], vbl + (kt + 1) * 64, SEQ);
            CP_COMMIT;
        }
        const int k0 = kt * 64, buf = kt & 1;
        float s[4][4];
        qk_mma(s, KhB[buf], KlB[buf]);

        // p = exp(s*scale) (unnormalized), accumulate l, write attn, pack bf16
        uint32_t php[4][2], plp[4][2];
#pragma unroll
        for (int nt = 0; nt < 4; ++nt) {
#pragma unroll
            for (int half = 0; half < 2; ++half) {
                int i = wm * 16 + cr + 8 * half;
                int j = wn * 32 + nt * 8 + 2 * cc;
                float p0 = 0.f, p1 = 0.f;
                if (k0 + j     <= q0 + i) p0 = __expf(s[nt][2 * half]     * scale);
                if (k0 + j + 1 <= q0 + i) p1 = __expf(s[nt][2 * half + 1] * scale);
                if (half) lp1 += p0 + p1; else lp0 += p0 + p1;
                if (write_attn)
                    *(float2*)(attn_base + (size_t)i * SEQ + k0 + j) = make_float2(p0, p1);
                bf16 h0, l0, h1, l1;
                split2(p0, h0, l0); split2(p1, h1, l1);
                php[nt][half] = pack2(h0, h1);
                plp[nt][half] = pack2(l0, l1);
            }
        }

        // O += P @ V over this warp's 32-wide j slice, all 64 d
#pragma unroll
        for (int kc = 0; kc < 2; ++kc) {
            uint32_t ah[4] = {php[2 * kc][0], php[2 * kc][1],
                              php[2 * kc + 1][0], php[2 * kc + 1][1]};
            uint32_t al[4] = {plp[2 * kc][0], plp[2 * kc][1],
                              plp[2 * kc + 1][0], plp[2 * kc + 1][1]};
#pragma unroll
            for (int g = 0; g < 4; ++g) {
                int row = g * 16 + 8 * (lm >> 1) + lr;
                int col = wn * 32 + kc * 16 + 8 * (lm & 1);
                uint32_t bh0, bh1, bh2, bh3, bl0, bl1, bl2, bl3;
                ldsm4(bh0, bh1, bh2, bh3, sptr(&VhB[buf][row * A_LDS + col]));
                ldsm4(bl0, bl1, bl2, bl3, sptr(&VlB[buf][row * A_LDS + col]));
                mma_bf16(o[2 * g],     ah, bh0, bh1);
                mma_bf16(o[2 * g],     ah, bl0, bl1);
                mma_bf16(o[2 * g],     al, bh0, bh1);
                mma_bf16(o[2 * g + 1], ah, bh2, bh3);
                mma_bf16(o[2 * g + 1], ah, bl2, bl3);
                mma_bf16(o[2 * g + 1], al, bh2, bh3);
            }
        }
    }

    // ---------------- l reduction -> linv (smem + global) -----------------
    lp0 += __shfl_xor_sync(0xffffffff, lp0, 1);
    lp0 += __shfl_xor_sync(0xffffffff, lp0, 2);
    lp1 += __shfl_xor_sync(0xffffffff, lp1, 1);
    lp1 += __shfl_xor_sync(0xffffffff, lp1, 2);
    if (cc == 0) {
        lsum[wn * 64 + wm * 16 + cr]     = lp0;
        lsum[wn * 64 + wm * 16 + cr + 8] = lp1;
    }
    __syncthreads();
    if (t < 64) {
        float li = 1.0f / (lsum[t] + lsum[64 + t]);
        lrow[t] = li;
        linv_g[bh * SEQ + q0 + t] = li;
    }
    __syncthreads();

    // ---------------- cross-warp O reduction + scale + store --------------
    if (wn == 1) {
#pragma unroll
        for (int nt = 0; nt < 8; ++nt)
#pragma unroll
            for (int half = 0; half < 2; ++half) {
                int i = wm * 16 + cr + 8 * half;
                int d = nt * 8 + 2 * cc;
                *(float2*)&red[i * 64 + d] =
                    make_float2(o[nt][2 * half], o[nt][2 * half + 1]);
            }
    }
    __syncthreads();
    if (wn == 0) {
        const float li0 = lrow[wm * 16 + cr];
        const float li1 = lrow[wm * 16 + cr + 8];
#pragma unroll
        for (int nt = 0; nt < 8; ++nt)
#pragma unroll
            for (int half = 0; half < 2; ++half) {
                int i = wm * 16 + cr + 8 * half;
                int d = nt * 8 + 2 * cc;
                float li = half ? li1 : li0;
                float2 rr = *(float2*)&red[i * 64 + d];
                float v0 = (o[nt][2 * half]     + rr.x) * li;
                float v1 = (o[nt][2 * half + 1] + rr.y) * li;
                bf16 h0, l0, h1, l1;
                split2(v0, h0, l0); split2(v1, h1, l1);
                size_t idx = (size_t)(b * SEQ + q0 + i) * DMODEL + h * DK + d;
                *(uint32_t*)(aoh + idx) = pack2(h0, h1);
                *(uint32_t*)(aol + idx) = pack2(l0, l1);
            }
    }
}

// ---------------------------------------------------------------------------
// attn_norm: scale causal prefix of each attn row by 1/l.
// ---------------------------------------------------------------------------
__global__ __launch_bounds__(256)
void attn_norm(float* __restrict__ attn, const float* __restrict__ linv_g)
{
    const int qt = (int)gridDim.x - 1 - (int)blockIdx.x;
    const int h = blockIdx.y, b = blockIdx.z;
    const size_t bh = (size_t)(b * NHEADS + h);
    const int q0 = qt * 64;
    const int r = threadIdx.x >> 2, sub = threadIdx.x & 3;
    const float li = linv_g[bh * SEQ + q0 + r];
    float* row = attn + (bh * SEQ + q0 + r) * (size_t)SEQ;
    const int L = q0 + 64;
    for (int c = sub * 4; c < L; c += 16) {
        float4 v = *(float4*)(row + c);
        v.x *= li; v.y *= li; v.z *= li; v.w *= li;
        *(float4*)(row + c) = v;
    }
}

// ---------------------------------------------------------------------------
// Launch
// ---------------------------------------------------------------------------
extern "C" void kernel_launch(void* const* d_in, const int* in_sizes, int n_in,
                              void* d_out, int out_size)
{
    const float* Q   = (const float*)d_in[0];
    const float* K   = (const float*)d_in[1];
    const float* V   = (const float*)d_in[2];
    const float* W_q = (const float*)d_in[3];
    const float* W_k = (const float*)d_in[4];
    const float* W_v = (const float*)d_in[5];
    const float* W_o = (const float*)d_in[6];
    const float* b_o = (const float*)d_in[7];
    float* out = (float*)d_out;

    const int write_attn = ((size_t)out_size > OUT_ELEMS) ? 1 : 0;
    float* attn = write_attn ? out + OUT_ELEMS : (float*)0;

    bf16 *qxh, *qxl, *kxh, *kxl, *vxh, *vxl;
    bf16 *wqh, *wql, *wkh, *wkl, *wvh, *wvl, *woh, *wol;
    bf16 *qh, *ql, *kh, *kl, *vh, *vl, *aoh, *aol;
    float* linv;
    cudaGetSymbolAddress((void**)&qxh, g_qxh); cudaGetSymbolAddress((void**)&qxl, g_qxl);
    cudaGetSymbolAddress((void**)&kxh, g_kxh); cudaGetSymbolAddress((void**)&kxl, g_kxl);
    cudaGetSymbolAddress((void**)&vxh, g_vxh); cudaGetSymbolAddress((void**)&vxl, g_vxl);
    cudaGetSymbolAddress((void**)&wqh, g_wqh); cudaGetSymbolAddress((void**)&wql, g_wql);
    cudaGetSymbolAddress((void**)&wkh, g_wkh); cudaGetSymbolAddress((void**)&wkl, g_wkl);
    cudaGetSymbolAddress((void**)&wvh, g_wvh); cudaGetSymbolAddress((void**)&wvl, g_wvl);
    cudaGetSymbolAddress((void**)&woh, g_woh); cudaGetSymbolAddress((void**)&wol, g_wol);
    cudaGetSymbolAddress((void**)&qh, g_qh);   cudaGetSymbolAddress((void**)&ql, g_ql);
    cudaGetSymbolAddress((void**)&kh, g_kh);   cudaGetSymbolAddress((void**)&kl, g_kl);
    cudaGetSymbolAddress((void**)&vh, g_vh);   cudaGetSymbolAddress((void**)&vl, g_vl);
    cudaGetSymbolAddress((void**)&aoh, g_aoh); cudaGetSymbolAddress((void**)&aol, g_aol);
    cudaGetSymbolAddress((void**)&linv, g_linv);

    cudaFuncSetAttribute(gemm_bf16<0>, cudaFuncAttributeMaxDynamicSharedMemorySize, SMEM_GEMM_BYTES);
    cudaFuncSetAttribute(gemm_bf16<1>, cudaFuncAttributeMaxDynamicSharedMemorySize, SMEM_GEMM_BYTES);
    cudaFuncSetAttribute(gemm_bf16<2>, cudaFuncAttributeMaxDynamicSharedMemorySize, SMEM_GEMM_BYTES);
    cudaFuncSetAttribute(attn_1p,      cudaFuncAttributeMaxDynamicSharedMemorySize, SMEM_ATTN_BYTES);

    const int n4x = MROWS * DMODEL / 4;
    const int n4w = DMODEL * DMODEL / 4;
    dim3 ggrid(DMODEL / 128, MROWS / 128);

    split_kernel<<<n4x / 256, 256>>>(Q,   qxh, qxl, n4x);
    split_kernel<<<n4x / 256, 256>>>(K,   kxh, kxl, n4x);
    split_kernel<<<n4x / 256, 256>>>(V,   vxh, vxl, n4x);
    split_kernel<<<n4w / 256, 256>>>(W_q, wqh, wql, n4w);
    split_kernel<<<n4w / 256, 256>>>(W_k, wkh, wkl, n4w);
    split_kernel<<<n4w / 256, 256>>>(W_v, wvh, wvl, n4w);
    split_kernel<<<n4w / 256, 256>>>(W_o, woh, wol, n4w);

    gemm_bf16<0><<<ggrid, 256, SMEM_GEMM_BYTES>>>(qxh, qxl, wqh, wql, (float*)0, (const float*)0, qh, ql);
    gemm_bf16<0><<<ggrid, 256, SMEM_GEMM_BYTES>>>(kxh, kxl, wkh, wkl, (float*)0, (const float*)0, kh, kl);
    gemm_bf16<1><<<ggrid, 256, SMEM_GEMM_BYTES>>>(vxh, vxl, wvh, wvl, (float*)0, (const float*)0, vh, vl);

    dim3 agrid(SEQ / 64, NHEADS, BATCH);
    attn_1p<<<agrid, 256, SMEM_ATTN_BYTES>>>(qh, ql, kh, kl, vh, vl, attn, aoh, aol, linv, write_attn);

    gemm_bf16<2><<<ggrid, 256, SMEM_GEMM_BYTES>>>(aoh, aol, woh, wol, out, b_o,
                                                  (bf16*)0, (bf16*)0);
    if (write_attn)
        attn_norm<<<agrid, 256>>>(attn, linv);
}

// round 7
// speedup vs baseline: 3.6354x; 1.3143x over previous
#include <cuda_runtime.h>
#include <cuda_fp16.h>
#include <stdint.h>

#define BATCH   2
#define SEQ     2048
#define DMODEL  1024
#define NHEADS  16
#define DK      64
#define MROWS   (BATCH * SEQ)                      // 4096
#define OUT_ELEMS ((size_t)MROWS * DMODEL)

typedef __half fp16;

// ---------------- scratch (device globals) ----------------
__device__ static fp16 g_qxh[MROWS * DMODEL], g_qxl[MROWS * DMODEL];
__device__ static fp16 g_kxh[MROWS * DMODEL], g_kxl[MROWS * DMODEL];
__device__ static fp16 g_vxh[MROWS * DMODEL], g_vxl[MROWS * DMODEL];
__device__ static fp16 g_wq[DMODEL * DMODEL], g_wk[DMODEL * DMODEL];
__device__ static fp16 g_wv[DMODEL * DMODEL], g_wo[DMODEL * DMODEL];
__device__ static fp16 g_qh[MROWS * DMODEL], g_ql[MROWS * DMODEL];   // q split [b][h][s][d]
__device__ static fp16 g_k [MROWS * DMODEL];                         // k single [b][h][s][d]
__device__ static fp16 g_v [MROWS * DMODEL];                         // v single [b][h][d][s]
__device__ static fp16 g_aoh[MROWS * DMODEL], g_aol[MROWS * DMODEL];
__device__ static float g_linv[BATCH * NHEADS * SEQ];

// ---------------- helpers ----------------
__device__ __forceinline__ uint32_t sptr(const void* p) {
    return (uint32_t)__cvta_generic_to_shared(p);
}
__device__ __forceinline__ void ldsm4(uint32_t& r0, uint32_t& r1, uint32_t& r2,
                                      uint32_t& r3, uint32_t a) {
    asm volatile("ldmatrix.sync.aligned.m8n8.x4.shared.b16 {%0,%1,%2,%3},[%4];"
                 : "=r"(r0), "=r"(r1), "=r"(r2), "=r"(r3) : "r"(a));
}
__device__ __forceinline__ void mma_f16(float c[4], const uint32_t a[4],
                                        uint32_t b0, uint32_t b1) {
    asm volatile(
        "mma.sync.aligned.m16n8k16.row.col.f32.f16.f16.f32 "
        "{%0,%1,%2,%3},{%4,%5,%6,%7},{%8,%9},{%0,%1,%2,%3};"
        : "+f"(c[0]), "+f"(c[1]), "+f"(c[2]), "+f"(c[3])
        : "r"(a[0]), "r"(a[1]), "r"(a[2]), "r"(a[3]), "r"(b0), "r"(b1));
}
__device__ __forceinline__ void split2(float x, fp16& h, fp16& l) {
    h = __float2half_rn(x);
    l = __float2half_rn(x - __half2float(h));
}
__device__ __forceinline__ uint32_t pack2(fp16 a, fp16 b) {
    __half2 t; t.x = a; t.y = b;
    return *(uint32_t*)&t;
}
__device__ __forceinline__ void cpa16(void* dst, const void* src) {
    asm volatile("cp.async.cg.shared.global [%0],[%1],16;"
                 :: "r"(sptr(dst)), "l"(__cvta_generic_to_global(src)));
}
#define CP_COMMIT  asm volatile("cp.async.commit_group;")
#define CP_WAIT0   asm volatile("cp.async.wait_group 0;")

// ---------------- split / convert kernels ----------------
__global__ __launch_bounds__(256)
void split_kernel(const float* __restrict__ in, fp16* __restrict__ oh,
                  fp16* __restrict__ ol, int n4)
{
    int i = blockIdx.x * blockDim.x + threadIdx.x;
    if (i >= n4) return;
    float4 v = ((const float4*)in)[i];
    fp16 h0, l0, h1, l1, h2, l2, h3, l3;
    split2(v.x, h0, l0); split2(v.y, h1, l1);
    split2(v.z, h2, l2); split2(v.w, h3, l3);
    ((uint2*)oh)[i] = make_uint2(pack2(h0, h1), pack2(h2, h3));
    ((uint2*)ol)[i] = make_uint2(pack2(l0, l1), pack2(l2, l3));
}
__global__ __launch_bounds__(256)
void cvt_kernel(const float* __restrict__ in, fp16* __restrict__ o, int n4)
{
    int i = blockIdx.x * blockDim.x + threadIdx.x;
    if (i >= n4) return;
    float4 v = ((const float4*)in)[i];
    ((uint2*)o)[i] = make_uint2(pack2(__float2half_rn(v.x), __float2half_rn(v.y)),
                                pack2(__float2half_rn(v.z), __float2half_rn(v.w)));
}

// ---------------------------------------------------------------------------
// GEMM: C[4096,1024] = A(split fp16) @ B(single fp16)^T. 128x128x32, 8 warps.
// 2 mma per logical mma.  EPI 0: split out [b][h][s][d]; 1: single [b][h][s][d];
// 2: single transposed [b][h][d][s]; 3: fp32 + bias.
// ---------------------------------------------------------------------------
#define G_LDS 40
#define G_TILE (128 * G_LDS)
#define SMEM_GEMM_BYTES (6 * G_TILE * 2)     // 61440

template <int EPI>
__global__ __launch_bounds__(256)
void gemm_fp16(const fp16* __restrict__ Ah, const fp16* __restrict__ Al,
               const fp16* __restrict__ Bw,
               float* __restrict__ Cout, const float* __restrict__ bias,
               fp16* __restrict__ oh, fp16* __restrict__ ol)
{
    extern __shared__ fp16 smg[];
    const int t = threadIdx.x;
    const int m0 = blockIdx.y * 128, n0 = blockIdx.x * 128;
    const int w = t >> 5, lane = t & 31;
    const int wm = w >> 2, wn = w & 3;
    const int lm = lane >> 3, lr = lane & 7;

    float acc[4][4][4];
#pragma unroll
    for (int i = 0; i < 4; ++i)
#pragma unroll
        for (int j = 0; j < 4; ++j)
#pragma unroll
            for (int e = 0; e < 4; ++e) acc[i][j][e] = 0.f;

    auto issue = [&](int kk) {
        fp16* d = smg + (kk & 1) * 3 * G_TILE;
        const fp16* srcs[3] = {
            Ah + (size_t)m0 * DMODEL + kk * 32, Al + (size_t)m0 * DMODEL + kk * 32,
            Bw + (size_t)n0 * DMODEL + kk * 32};
        const int r = t >> 2, o = (t & 3) * 8;
#pragma unroll
        for (int tl = 0; tl < 3; ++tl) {
            cpa16(d + tl * G_TILE + r * G_LDS + o,        srcs[tl] + (size_t)r * DMODEL + o);
            cpa16(d + tl * G_TILE + (r + 64) * G_LDS + o, srcs[tl] + (size_t)(r + 64) * DMODEL + o);
        }
    };

    issue(0); CP_COMMIT;

    const int NK = DMODEL / 32;
    for (int kk = 0; kk < NK; ++kk) {
        CP_WAIT0;
        __syncthreads();
        if (kk + 1 < NK) { issue(kk + 1); CP_COMMIT; }
        const fp16* sAh = smg + (kk & 1) * 3 * G_TILE;
        const fp16* sAl = sAh + G_TILE;
        const fp16* sB  = sAl + G_TILE;
#pragma unroll
        for (int k16 = 0; k16 < 32; k16 += 16) {
            uint32_t ah[4][4], al[4][4], bh[4][2];
#pragma unroll
            for (int mt = 0; mt < 4; ++mt) {
                int row = wm * 64 + mt * 16 + lr + 8 * (lm & 1);
                int col = k16 + 8 * (lm >> 1);
                ldsm4(ah[mt][0], ah[mt][1], ah[mt][2], ah[mt][3], sptr(&sAh[row * G_LDS + col]));
                ldsm4(al[mt][0], al[mt][1], al[mt][2], al[mt][3], sptr(&sAl[row * G_LDS + col]));
            }
#pragma unroll
            for (int g = 0; g < 2; ++g) {
                int row = wn * 32 + g * 16 + 8 * (lm >> 1) + lr;
                int col = k16 + 8 * (lm & 1);
                ldsm4(bh[2 * g][0], bh[2 * g][1], bh[2 * g + 1][0], bh[2 * g + 1][1],
                      sptr(&sB[row * G_LDS + col]));
            }
#pragma unroll
            for (int mt = 0; mt < 4; ++mt)
#pragma unroll
                for (int nt = 0; nt < 4; ++nt) {
                    mma_f16(acc[mt][nt], ah[mt], bh[nt][0], bh[nt][1]);
                    mma_f16(acc[mt][nt], al[mt], bh[nt][0], bh[nt][1]);
                }
        }
    }

    const int cr = lane >> 2, cc = lane & 3;
#pragma unroll
    for (int mt = 0; mt < 4; ++mt)
#pragma unroll
        for (int nt = 0; nt < 4; ++nt)
#pragma unroll
            for (int half = 0; half < 2; ++half) {
                int gm = m0 + wm * 64 + mt * 16 + cr + 8 * half;
                int gn = n0 + wn * 32 + nt * 8 + 2 * cc;
                float v0 = acc[mt][nt][2 * half + 0];
                float v1 = acc[mt][nt][2 * half + 1];
                if (EPI == 3) {
                    *(float2*)(Cout + (size_t)gm * DMODEL + gn) =
                        make_float2(v0 + bias[gn], v1 + bias[gn + 1]);
                } else {
                    int b = gm >> 11, s = gm & 2047, h = gn >> 6, d = gn & 63;
                    if (EPI == 0) {
                        fp16 h0, l0, h1, l1;
                        split2(v0, h0, l0); split2(v1, h1, l1);
                        size_t idx = (((size_t)(b * NHEADS + h) * SEQ) + s) * DK + d;
                        *(uint32_t*)(oh + idx) = pack2(h0, h1);
                        *(uint32_t*)(ol + idx) = pack2(l0, l1);
                    } else if (EPI == 1) {
                        size_t idx = (((size_t)(b * NHEADS + h) * SEQ) + s) * DK + d;
                        *(uint32_t*)(oh + idx) = pack2(__float2half_rn(v0), __float2half_rn(v1));
                    } else {
                        size_t idx = (((size_t)(b * NHEADS + h) * DK) + d) * SEQ + s;
                        oh[idx]       = __float2half_rn(v0);
                        oh[idx + SEQ] = __float2half_rn(v1);
                    }
                }
            }
}

// ---------------------------------------------------------------------------
// Single-pass attention (m == 0), fp16x2: Q split in smem, K/V single.
// 8 warps: wm = w>>1 (16-row slice), wn = w&1 (32-wide j slice).
// ---------------------------------------------------------------------------
#define A_LDS 72
#define A_TILE (64 * A_LDS)
#define SMEM_ATTN_BYTES (6 * A_TILE * 2 + 128 * 4 + 64 * 4)   // 56064

__global__ __launch_bounds__(256, 2)
void attn_1p(const fp16* __restrict__ qh, const fp16* __restrict__ ql,
             const fp16* __restrict__ kk_g, const fp16* __restrict__ vv_g,
             float* __restrict__ attn, fp16* __restrict__ aoh,
             fp16* __restrict__ aol, float* __restrict__ linv_g,
             int write_attn)
{
    extern __shared__ fp16 sma[];
    fp16* Qh = sma;
    fp16* Ql = sma + A_TILE;
    fp16* KB[2] = {sma + 2 * A_TILE, sma + 3 * A_TILE};
    fp16* VB[2] = {sma + 4 * A_TILE, sma + 5 * A_TILE};
    float* lsum = (float*)(sma + 6 * A_TILE);    // [2][64]
    float* lrow = lsum + 128;                    // [64]
    float* red  = (float*)(sma + 2 * A_TILE);    // aliases K/V bufs (end only)

    const int qt = (int)gridDim.x - 1 - (int)blockIdx.x;   // heavy first
    const int h = blockIdx.y, b = blockIdx.z;
    const int q0 = qt * 64;
    const int t = threadIdx.x, w = t >> 5, lane = t & 31;
    const int wm = w >> 1, wn = w & 1;
    const int lm = lane >> 3, lr = lane & 7;
    const int cr = lane >> 2, cc = lane & 3;
    const float scale = 0.125f;

    const size_t bh = (size_t)(b * NHEADS + h);
    const fp16* qbh = qh + bh * SEQ * DK;
    const fp16* qbl = ql + bh * SEQ * DK;
    const fp16* kb  = kk_g + bh * SEQ * DK;
    const fp16* vb  = vv_g + bh * DK * SEQ;

    auto cpa_tile = [&](fp16* dst, const fp16* src, int rstride) {
        const int r = t >> 3, o = (t & 7) * 8;
        cpa16(dst + r * A_LDS + o,        src + (size_t)r * rstride + o);
        cpa16(dst + (r + 32) * A_LDS + o, src + (size_t)(r + 32) * rstride + o);
    };

    auto qk_mma = [&](float s[4][4], const fp16* KT) {
#pragma unroll
        for (int nt = 0; nt < 4; ++nt)
#pragma unroll
            for (int e = 0; e < 4; ++e) s[nt][e] = 0.f;
#pragma unroll
        for (int kc = 0; kc < 4; ++kc) {
            uint32_t af[4], alf[4], bfh[4][2];
            {
                int row = wm * 16 + lr + 8 * (lm & 1);
                int col = kc * 16 + 8 * (lm >> 1);
                ldsm4(af[0], af[1], af[2], af[3], sptr(&Qh[row * A_LDS + col]));
                ldsm4(alf[0], alf[1], alf[2], alf[3], sptr(&Ql[row * A_LDS + col]));
            }
#pragma unroll
            for (int g = 0; g < 2; ++g) {
                int row = wn * 32 + g * 16 + 8 * (lm >> 1) + lr;
                int col = kc * 16 + 8 * (lm & 1);
                ldsm4(bfh[2 * g][0], bfh[2 * g][1], bfh[2 * g + 1][0], bfh[2 * g + 1][1],
                      sptr(&KT[row * A_LDS + col]));
            }
#pragma unroll
            for (int nt = 0; nt < 4; ++nt) {
                mma_f16(s[nt], af,  bfh[nt][0], bfh[nt][1]);
                mma_f16(s[nt], alf, bfh[nt][0], bfh[nt][1]);
            }
        }
    };

    // prologue: Q, K(0), V(0)
    cpa_tile(Qh, qbh + (size_t)q0 * DK, DK);
    cpa_tile(Ql, qbl + (size_t)q0 * DK, DK);
    cpa_tile(KB[0], kb, DK);
    cpa_tile(VB[0], vb, SEQ);
    CP_COMMIT;

    float* attn_base = write_attn ? attn + (bh * SEQ + q0) * SEQ : (float*)0;
    if (write_attn) {   // zero fully-masked tiles (overlaps cp.async)
        const int zr = t >> 2, zc = (t & 3) * 16;
        for (int kt = qt + 1; kt < SEQ / 64; ++kt) {
            float4 z = make_float4(0.f, 0.f, 0.f, 0.f);
            float* dst = attn_base + (size_t)zr * SEQ + kt * 64 + zc;
            *(float4*)(dst) = z; *(float4*)(dst + 4) = z;
            *(float4*)(dst + 8) = z; *(float4*)(dst + 12) = z;
        }
    }

    float o[8][4];
#pragma unroll
    for (int nt = 0; nt < 8; ++nt)
#pragma unroll
        for (int e = 0; e < 4; ++e) o[nt][e] = 0.f;
    float lp0 = 0.f, lp1 = 0.f;

    for (int kt = 0; kt <= qt; ++kt) {
        CP_WAIT0;
        __syncthreads();
        if (kt + 1 <= qt) {
            cpa_tile(KB[(kt + 1) & 1], kb + (size_t)(kt + 1) * 64 * DK, DK);
            cpa_tile(VB[(kt + 1) & 1], vb + (kt + 1) * 64, SEQ);
            CP_COMMIT;
        }
        const int k0 = kt * 64, buf = kt & 1;
        float s[4][4];
        qk_mma(s, KB[buf]);

        uint32_t php[4][2], plp[4][2];
#pragma unroll
        for (int nt = 0; nt < 4; ++nt) {
#pragma unroll
            for (int half = 0; half < 2; ++half) {
                int i = wm * 16 + cr + 8 * half;
                int j = wn * 32 + nt * 8 + 2 * cc;
                float p0 = 0.f, p1 = 0.f;
                if (k0 + j     <= q0 + i) p0 = __expf(s[nt][2 * half]     * scale);
                if (k0 + j + 1 <= q0 + i) p1 = __expf(s[nt][2 * half + 1] * scale);
                if (half) lp1 += p0 + p1; else lp0 += p0 + p1;
                if (write_attn)
                    *(float2*)(attn_base + (size_t)i * SEQ + k0 + j) = make_float2(p0, p1);
                fp16 h0, l0, h1, l1;
                split2(p0, h0, l0); split2(p1, h1, l1);
                php[nt][half] = pack2(h0, h1);
                plp[nt][half] = pack2(l0, l1);
            }
        }

#pragma unroll
        for (int kc = 0; kc < 2; ++kc) {
            uint32_t ah[4] = {php[2 * kc][0], php[2 * kc][1],
                              php[2 * kc + 1][0], php[2 * kc + 1][1]};
            uint32_t al[4] = {plp[2 * kc][0], plp[2 * kc][1],
                              plp[2 * kc + 1][0], plp[2 * kc + 1][1]};
#pragma unroll
            for (int g = 0; g < 4; ++g) {
                int row = g * 16 + 8 * (lm >> 1) + lr;
                int col = wn * 32 + kc * 16 + 8 * (lm & 1);
                uint32_t bh0, bh1, bh2, bh3;
                ldsm4(bh0, bh1, bh2, bh3, sptr(&VB[buf][row * A_LDS + col]));
                mma_f16(o[2 * g],     ah, bh0, bh1);
                mma_f16(o[2 * g],     al, bh0, bh1);
                mma_f16(o[2 * g + 1], ah, bh2, bh3);
                mma_f16(o[2 * g + 1], al, bh2, bh3);
            }
        }
    }

    // ---------------- l reduction -> linv ----------------
    lp0 += __shfl_xor_sync(0xffffffff, lp0, 1);
    lp0 += __shfl_xor_sync(0xffffffff, lp0, 2);
    lp1 += __shfl_xor_sync(0xffffffff, lp1, 1);
    lp1 += __shfl_xor_sync(0xffffffff, lp1, 2);
    if (cc == 0) {
        lsum[wn * 64 + wm * 16 + cr]     = lp0;
        lsum[wn * 64 + wm * 16 + cr + 8] = lp1;
    }
    __syncthreads();
    if (t < 64) {
        float li = 1.0f / (lsum[t] + lsum[64 + t]);
        lrow[t] = li;
        linv_g[bh * SEQ + q0 + t] = li;
    }
    __syncthreads();

    // ---------------- cross-warp O reduction + scale + store --------------
    if (wn == 1) {
#pragma unroll
        for (int nt = 0; nt < 8; ++nt)
#pragma unroll
            for (int half = 0; half < 2; ++half) {
                int i = wm * 16 + cr + 8 * half;
                int d = nt * 8 + 2 * cc;
                *(float2*)&red[i * 64 + d] =
                    make_float2(o[nt][2 * half], o[nt][2 * half + 1]);
            }
    }
    __syncthreads();
    if (wn == 0) {
        const float li0 = lrow[wm * 16 + cr];
        const float li1 = lrow[wm * 16 + cr + 8];
#pragma unroll
        for (int nt = 0; nt < 8; ++nt)
#pragma unroll
            for (int half = 0; half < 2; ++half) {
                int i = wm * 16 + cr + 8 * half;
                int d = nt * 8 + 2 * cc;
                float li = half ? li1 : li0;
                float2 rr = *(float2*)&red[i * 64 + d];
                float v0 = (o[nt][2 * half]     + rr.x) * li;
                float v1 = (o[nt][2 * half + 1] + rr.y) * li;
                fp16 h0, l0, h1, l1;
                split2(v0, h0, l0); split2(v1, h1, l1);
                size_t idx = (size_t)(b * SEQ + q0 + i) * DMODEL + h * DK + d;
                *(uint32_t*)(aoh + idx) = pack2(h0, h1);
                *(uint32_t*)(aol + idx) = pack2(l0, l1);
            }
    }
}

// ---------------------------------------------------------------------------
// attn_norm: scale causal prefix of each attn row by 1/l.
// ---------------------------------------------------------------------------
__global__ __launch_bounds__(256)
void attn_norm(float* __restrict__ attn, const float* __restrict__ linv_g)
{
    const int qt = (int)gridDim.x - 1 - (int)blockIdx.x;
    const int h = blockIdx.y, b = blockIdx.z;
    const size_t bh = (size_t)(b * NHEADS + h);
    const int q0 = qt * 64;
    const int r = threadIdx.x >> 2, sub = threadIdx.x & 3;
    const float li = linv_g[bh * SEQ + q0 + r];
    float* row = attn + (bh * SEQ + q0 + r) * (size_t)SEQ;
    const int L = q0 + 64;
    for (int c = sub * 4; c < L; c += 16) {
        float4 v = *(float4*)(row + c);
        v.x *= li; v.y *= li; v.z *= li; v.w *= li;
        *(float4*)(row + c) = v;
    }
}

// ---------------------------------------------------------------------------
// Launch
// ---------------------------------------------------------------------------
extern "C" void kernel_launch(void* const* d_in, const int* in_sizes, int n_in,
                              void* d_out, int out_size)
{
    const float* Q   = (const float*)d_in[0];
    const float* K   = (const float*)d_in[1];
    const float* V   = (const float*)d_in[2];
    const float* W_q = (const float*)d_in[3];
    const float* W_k = (const float*)d_in[4];
    const float* W_v = (const float*)d_in[5];
    const float* W_o = (const float*)d_in[6];
    const float* b_o = (const float*)d_in[7];
    float* out = (float*)d_out;

    const int write_attn = ((size_t)out_size > OUT_ELEMS) ? 1 : 0;
    float* attn = write_attn ? out + OUT_ELEMS : (float*)0;

    fp16 *qxh, *qxl, *kxh, *kxl, *vxh, *vxl;
    fp16 *wq, *wk, *wv, *wo;
    fp16 *qh, *ql, *kkp, *vvp, *aoh, *aol;
    float* linv;
    cudaGetSymbolAddress((void**)&qxh, g_qxh); cudaGetSymbolAddress((void**)&qxl, g_qxl);
    cudaGetSymbolAddress((void**)&kxh, g_kxh); cudaGetSymbolAddress((void**)&kxl, g_kxl);
    cudaGetSymbolAddress((void**)&vxh, g_vxh); cudaGetSymbolAddress((void**)&vxl, g_vxl);
    cudaGetSymbolAddress((void**)&wq, g_wq);   cudaGetSymbolAddress((void**)&wk, g_wk);
    cudaGetSymbolAddress((void**)&wv, g_wv);   cudaGetSymbolAddress((void**)&wo, g_wo);
    cudaGetSymbolAddress((void**)&qh, g_qh);   cudaGetSymbolAddress((void**)&ql, g_ql);
    cudaGetSymbolAddress((void**)&kkp, g_k);   cudaGetSymbolAddress((void**)&vvp, g_v);
    cudaGetSymbolAddress((void**)&aoh, g_aoh); cudaGetSymbolAddress((void**)&aol, g_aol);
    cudaGetSymbolAddress((void**)&linv, g_linv);

    cudaFuncSetAttribute(gemm_fp16<0>, cudaFuncAttributeMaxDynamicSharedMemorySize, SMEM_GEMM_BYTES);
    cudaFuncSetAttribute(gemm_fp16<1>, cudaFuncAttributeMaxDynamicSharedMemorySize, SMEM_GEMM_BYTES);
    cudaFuncSetAttribute(gemm_fp16<2>, cudaFuncAttributeMaxDynamicSharedMemorySize, SMEM_GEMM_BYTES);
    cudaFuncSetAttribute(gemm_fp16<3>, cudaFuncAttributeMaxDynamicSharedMemorySize, SMEM_GEMM_BYTES);
    cudaFuncSetAttribute(attn_1p,      cudaFuncAttributeMaxDynamicSharedMemorySize, SMEM_ATTN_BYTES);

    const int n4x = MROWS * DMODEL / 4;
    const int n4w = DMODEL * DMODEL / 4;
    dim3 ggrid(DMODEL / 128, MROWS / 128);

    split_kernel<<<n4x / 256, 256>>>(Q, qxh, qxl, n4x);
    split_kernel<<<n4x / 256, 256>>>(K, kxh, kxl, n4x);
    split_kernel<<<n4x / 256, 256>>>(V, vxh, vxl, n4x);
    cvt_kernel<<<n4w / 256, 256>>>(W_q, wq, n4w);
    cvt_kernel<<<n4w / 256, 256>>>(W_k, wk, n4w);
    cvt_kernel<<<n4w / 256, 256>>>(W_v, wv, n4w);
    cvt_kernel<<<n4w / 256, 256>>>(W_o, wo, n4w);

    gemm_fp16<0><<<ggrid, 256, SMEM_GEMM_BYTES>>>(qxh, qxl, wq, (float*)0, (const float*)0, qh, ql);
    gemm_fp16<1><<<ggrid, 256, SMEM_GEMM_BYTES>>>(kxh, kxl, wk, (float*)0, (const float*)0, kkp, (fp16*)0);
    gemm_fp16<2><<<ggrid, 256, SMEM_GEMM_BYTES>>>(vxh, vxl, wv, (float*)0, (const float*)0, vvp, (fp16*)0);

    dim3 agrid(SEQ / 64, NHEADS, BATCH);
    attn_1p<<<agrid, 256, SMEM_ATTN_BYTES>>>(qh, ql, kkp, vvp, attn, aoh, aol, linv, write_attn);

    gemm_fp16<3><<<ggrid, 256, SMEM_GEMM_BYTES>>>(aoh, aol, wo, out, b_o, (fp16*)0, (fp16*)0);
    if (write_attn)
        attn_norm<<<agrid, 256>>>(attn, linv);
}